// round 1
// baseline (speedup 1.0000x reference)
#include <cuda_runtime.h>
#include <cstdint>

#define B_TOK 8192
#define DDIM  1024
#define HDIM  2048
#define ODIM  1024
#define NEXP  8

// -------- scratch (device globals: allocation-free rule) --------
__device__ int   g_count[NEXP];
__device__ int   g_list[NEXP * B_TOK];     // entry = token*2 + slot
__device__ float g_wlist[NEXP * B_TOK];
__device__ float g_h[(size_t)2 * B_TOK * HDIM];     // [16384, 2048] hidden rows
__device__ float g_part[(size_t)2 * B_TOK * ODIM];  // [16384, 1024] weighted partials

// -------- packed f32x2 helpers (Blackwell FFMA2 path) --------
__device__ __forceinline__ unsigned long long pack2(float lo, float hi) {
    unsigned long long r;
    asm("mov.b64 %0, {%1, %2};" : "=l"(r) : "f"(lo), "f"(hi));
    return r;
}
__device__ __forceinline__ void ffma2(unsigned long long& d, unsigned long long a,
                                      unsigned long long b) {
    asm("fma.rn.f32x2 %0, %1, %2, %0;" : "+l"(d) : "l"(a), "l"(b));
}
__device__ __forceinline__ float2 unpack2(unsigned long long v) {
    float2 r;
    asm("mov.b64 {%0, %1}, %2;" : "=f"(r.x), "=f"(r.y) : "l"(v));
    return r;
}

// ============================ gating ============================
__global__ void zero_counts_kernel() {
    if (threadIdx.x < NEXP) g_count[threadIdx.x] = 0;
}

__global__ void gate_kernel(const float* __restrict__ x,
                            const float* __restrict__ Wg,
                            const float* __restrict__ bg) {
    int gw   = (blockIdx.x * blockDim.x + threadIdx.x) >> 5;  // token
    int lane = threadIdx.x & 31;
    if (gw >= B_TOK) return;
    const float* xr = x + (size_t)gw * DDIM;

    float acc[NEXP];
#pragma unroll
    for (int e = 0; e < NEXP; e++) acc[e] = 0.f;

    for (int d = lane; d < DDIM; d += 32) {
        float xv = xr[d];
        const float4* w4 = reinterpret_cast<const float4*>(Wg + (size_t)d * NEXP);
        float4 w0 = w4[0], w1 = w4[1];
        acc[0] += xv * w0.x; acc[1] += xv * w0.y;
        acc[2] += xv * w0.z; acc[3] += xv * w0.w;
        acc[4] += xv * w1.x; acc[5] += xv * w1.y;
        acc[6] += xv * w1.z; acc[7] += xv * w1.w;
    }
#pragma unroll
    for (int off = 16; off; off >>= 1)
#pragma unroll
        for (int e = 0; e < NEXP; e++)
            acc[e] += __shfl_xor_sync(0xFFFFFFFFu, acc[e], off);

    if (lane == 0) {
        float s[NEXP];
#pragma unroll
        for (int e = 0; e < NEXP; e++) s[e] = acc[e] + bg[e];
        float M = s[0];
#pragma unroll
        for (int e = 1; e < NEXP; e++) M = fmaxf(M, s[e]);
        float p[NEXP], Z = 0.f;
#pragma unroll
        for (int e = 0; e < NEXP; e++) { p[e] = expf(s[e] - M); Z += p[e]; }
        // top-2, first-index-wins on ties (matches jax.lax.top_k)
        int i1 = 0;
#pragma unroll
        for (int e = 1; e < NEXP; e++) if (s[e] > s[i1]) i1 = e;
        int i2 = -1;
#pragma unroll
        for (int e = 0; e < NEXP; e++)
            if (e != i1 && (i2 < 0 || s[e] > s[i2])) i2 = e;
        // weights = softmax masked to top-k, renormalized with +1e-8 (on normalized p)
        float denom = p[i1] + p[i2] + 1e-8f * Z;
        float w1 = p[i1] / denom;
        float w2 = p[i2] / denom;
        int pos1 = atomicAdd(&g_count[i1], 1);
        g_list[i1 * B_TOK + pos1]  = gw * 2 + 0;
        g_wlist[i1 * B_TOK + pos1] = w1;
        int pos2 = atomicAdd(&g_count[i2], 1);
        g_list[i2 * B_TOK + pos2]  = gw * 2 + 1;
        g_wlist[i2 * B_TOK + pos2] = w2;
    }
}

// ============================ GEMM1: h = relu(x_g @ W1[e] + b1[e]) ============
// 128x128 tile, TK=8, 256 threads, 8x8 micro-tile via f32x2 packed FMA.
__global__ __launch_bounds__(256, 2)
void gemm1_kernel(const float* __restrict__ x,
                  const float* __restrict__ W1,
                  const float* __restrict__ b1) {
    const int e     = blockIdx.z;
    const int count = g_count[e];
    const int r0    = blockIdx.y * 128;
    if (r0 >= count) return;
    const int n0 = blockIdx.x * 128;

    __shared__ float As[8][128];
    __shared__ float Bs[8][128];
    __shared__ int   sEnt[128];

    const int t = threadIdx.x;
    if (t < 128) {
        int pos = r0 + t;
        sEnt[t] = (pos < count) ? g_list[e * B_TOK + pos] : -1;
    }
    __syncthreads();

    const int ar = t >> 1;
    const int ac = (t & 1) * 4;
    int entA = sEnt[ar];
    const float* aRow = x + (size_t)(entA < 0 ? 0 : (entA >> 1)) * DDIM;

    const int br = t >> 5;
    const int bc = (t & 31) * 4;
    const float* bBase = W1 + (size_t)e * DDIM * HDIM + (size_t)br * HDIM + n0 + bc;

    const int ty = t >> 4, tx = t & 15;
    const int m0 = ty * 8, nn0 = tx * 8;

    unsigned long long acc2[8][4];
#pragma unroll
    for (int i = 0; i < 8; i++)
#pragma unroll
        for (int j = 0; j < 4; j++) acc2[i][j] = 0ull;

    float4 avN = *reinterpret_cast<const float4*>(aRow + ac);
    float4 bvN = *reinterpret_cast<const float4*>(bBase);

    for (int kt = 0; kt < DDIM; kt += 8) {
        float4 av = avN, bv = bvN;
        int ktn = (kt + 8 < DDIM) ? kt + 8 : kt;
        avN = *reinterpret_cast<const float4*>(aRow + ktn + ac);
        bvN = *reinterpret_cast<const float4*>(bBase + (size_t)ktn * HDIM);

        __syncthreads();
        As[ac + 0][ar] = av.x; As[ac + 1][ar] = av.y;
        As[ac + 2][ar] = av.z; As[ac + 3][ar] = av.w;
        *reinterpret_cast<float4*>(&Bs[br][bc]) = bv;
        __syncthreads();

#pragma unroll
        for (int k = 0; k < 8; k++) {
            float4 a0  = *reinterpret_cast<const float4*>(&As[k][m0]);
            float4 a1  = *reinterpret_cast<const float4*>(&As[k][m0 + 4]);
            float4 b0  = *reinterpret_cast<const float4*>(&Bs[k][nn0]);
            float4 b1v = *reinterpret_cast<const float4*>(&Bs[k][nn0 + 4]);
            unsigned long long b2[4];
            b2[0] = pack2(b0.x, b0.y);  b2[1] = pack2(b0.z, b0.w);
            b2[2] = pack2(b1v.x, b1v.y); b2[3] = pack2(b1v.z, b1v.w);
            float am[8] = {a0.x, a0.y, a0.z, a0.w, a1.x, a1.y, a1.z, a1.w};
#pragma unroll
            for (int i = 0; i < 8; i++) {
                unsigned long long a2 = pack2(am[i], am[i]);
                ffma2(acc2[i][0], a2, b2[0]);
                ffma2(acc2[i][1], a2, b2[1]);
                ffma2(acc2[i][2], a2, b2[2]);
                ffma2(acc2[i][3], a2, b2[3]);
            }
        }
    }

    // epilogue: + b1, relu, scatter to g_h rows
    const float* b1p = b1 + (size_t)e * HDIM + n0 + nn0;
    float4 bb0 = *reinterpret_cast<const float4*>(b1p);
    float4 bb1 = *reinterpret_cast<const float4*>(b1p + 4);
#pragma unroll
    for (int i = 0; i < 8; i++) {
        int ent = sEnt[m0 + i];
        if (ent < 0) continue;
        float* hp = g_h + (size_t)ent * HDIM + n0 + nn0;
        float2 v0 = unpack2(acc2[i][0]), v1 = unpack2(acc2[i][1]);
        float2 v2 = unpack2(acc2[i][2]), v3 = unpack2(acc2[i][3]);
        float4 o0, o1;
        o0.x = fmaxf(v0.x + bb0.x, 0.f); o0.y = fmaxf(v0.y + bb0.y, 0.f);
        o0.z = fmaxf(v1.x + bb0.z, 0.f); o0.w = fmaxf(v1.y + bb0.w, 0.f);
        o1.x = fmaxf(v2.x + bb1.x, 0.f); o1.y = fmaxf(v2.y + bb1.y, 0.f);
        o1.z = fmaxf(v3.x + bb1.z, 0.f); o1.w = fmaxf(v3.y + bb1.w, 0.f);
        *reinterpret_cast<float4*>(hp)     = o0;
        *reinterpret_cast<float4*>(hp + 4) = o1;
    }
}

// ============================ GEMM2: part = w * (h @ W2[e] + b2[e]) ===========
__global__ __launch_bounds__(256, 2)
void gemm2_kernel(const float* __restrict__ W2,
                  const float* __restrict__ b2) {
    const int e     = blockIdx.z;
    const int count = g_count[e];
    const int r0    = blockIdx.y * 128;
    if (r0 >= count) return;
    const int n0 = blockIdx.x * 128;

    __shared__ float As[8][128];
    __shared__ float Bs[8][128];
    __shared__ int   sEnt[128];
    __shared__ float sW[128];

    const int t = threadIdx.x;
    if (t < 128) {
        int pos = r0 + t;
        bool ok = (pos < count);
        sEnt[t] = ok ? g_list[e * B_TOK + pos] : -1;
        sW[t]   = ok ? g_wlist[e * B_TOK + pos] : 0.f;
    }
    __syncthreads();

    const int ar = t >> 1;
    const int ac = (t & 1) * 4;
    int entA = sEnt[ar];
    const float* aRow = g_h + (size_t)(entA < 0 ? 0 : entA) * HDIM;

    const int br = t >> 5;
    const int bc = (t & 31) * 4;
    const float* bBase = W2 + (size_t)e * HDIM * ODIM + (size_t)br * ODIM + n0 + bc;

    const int ty = t >> 4, tx = t & 15;
    const int m0 = ty * 8, nn0 = tx * 8;

    unsigned long long acc2[8][4];
#pragma unroll
    for (int i = 0; i < 8; i++)
#pragma unroll
        for (int j = 0; j < 4; j++) acc2[i][j] = 0ull;

    float4 avN = *reinterpret_cast<const float4*>(aRow + ac);
    float4 bvN = *reinterpret_cast<const float4*>(bBase);

    for (int kt = 0; kt < HDIM; kt += 8) {
        float4 av = avN, bv = bvN;
        int ktn = (kt + 8 < HDIM) ? kt + 8 : kt;
        avN = *reinterpret_cast<const float4*>(aRow + ktn + ac);
        bvN = *reinterpret_cast<const float4*>(bBase + (size_t)ktn * ODIM);

        __syncthreads();
        As[ac + 0][ar] = av.x; As[ac + 1][ar] = av.y;
        As[ac + 2][ar] = av.z; As[ac + 3][ar] = av.w;
        *reinterpret_cast<float4*>(&Bs[br][bc]) = bv;
        __syncthreads();

#pragma unroll
        for (int k = 0; k < 8; k++) {
            float4 a0  = *reinterpret_cast<const float4*>(&As[k][m0]);
            float4 a1  = *reinterpret_cast<const float4*>(&As[k][m0 + 4]);
            float4 b0  = *reinterpret_cast<const float4*>(&Bs[k][nn0]);
            float4 b1v = *reinterpret_cast<const float4*>(&Bs[k][nn0 + 4]);
            unsigned long long bp[4];
            bp[0] = pack2(b0.x, b0.y);  bp[1] = pack2(b0.z, b0.w);
            bp[2] = pack2(b1v.x, b1v.y); bp[3] = pack2(b1v.z, b1v.w);
            float am[8] = {a0.x, a0.y, a0.z, a0.w, a1.x, a1.y, a1.z, a1.w};
#pragma unroll
            for (int i = 0; i < 8; i++) {
                unsigned long long a2 = pack2(am[i], am[i]);
                ffma2(acc2[i][0], a2, bp[0]);
                ffma2(acc2[i][1], a2, bp[1]);
                ffma2(acc2[i][2], a2, bp[2]);
                ffma2(acc2[i][3], a2, bp[3]);
            }
        }
    }

    const float* b2p = b2 + (size_t)e * ODIM + n0 + nn0;
    float4 bb0 = *reinterpret_cast<const float4*>(b2p);
    float4 bb1 = *reinterpret_cast<const float4*>(b2p + 4);
#pragma unroll
    for (int i = 0; i < 8; i++) {
        int ent = sEnt[m0 + i];
        if (ent < 0) continue;
        float w = sW[m0 + i];
        float* pp = g_part + (size_t)ent * ODIM + n0 + nn0;
        float2 v0 = unpack2(acc2[i][0]), v1 = unpack2(acc2[i][1]);
        float2 v2 = unpack2(acc2[i][2]), v3 = unpack2(acc2[i][3]);
        float4 o0, o1;
        o0.x = (v0.x + bb0.x) * w; o0.y = (v0.y + bb0.y) * w;
        o0.z = (v1.x + bb0.z) * w; o0.w = (v1.y + bb0.w) * w;
        o1.x = (v2.x + bb1.x) * w; o1.y = (v2.y + bb1.y) * w;
        o1.z = (v3.x + bb1.z) * w; o1.w = (v3.y + bb1.w) * w;
        *reinterpret_cast<float4*>(pp)     = o0;
        *reinterpret_cast<float4*>(pp + 4) = o1;
    }
}

// ============================ combine ============================
__global__ void combine_kernel(float* __restrict__ out) {
    int idx = blockIdx.x * blockDim.x + threadIdx.x;  // over B*ODIM/4 float4s
    const int OW = ODIM / 4;
    int b  = idx / OW;
    int o4 = idx - b * OW;
    const float4* p = reinterpret_cast<const float4*>(g_part);
    float4 u = p[(size_t)(2 * b) * OW + o4];
    float4 v = p[(size_t)(2 * b + 1) * OW + o4];
    float4 r;
    r.x = u.x + v.x; r.y = u.y + v.y; r.z = u.z + v.z; r.w = u.w + v.w;
    reinterpret_cast<float4*>(out)[idx] = r;
}

// ============================ launch ============================
extern "C" void kernel_launch(void* const* d_in, const int* in_sizes, int n_in,
                              void* d_out, int out_size) {
    const float* x  = (const float*)d_in[0];
    const float* Wg = (const float*)d_in[1];
    const float* bg = (const float*)d_in[2];
    const float* W1 = (const float*)d_in[3];
    const float* b1 = (const float*)d_in[4];
    const float* W2 = (const float*)d_in[5];
    const float* b2 = (const float*)d_in[6];
    float* out = (float*)d_out;

    zero_counts_kernel<<<1, 32>>>();
    gate_kernel<<<B_TOK / 8, 256>>>(x, Wg, bg);

    dim3 g1(HDIM / 128, B_TOK / 128, NEXP);
    gemm1_kernel<<<g1, 256>>>(x, W1, b1);

    dim3 g2(ODIM / 128, B_TOK / 128, NEXP);
    gemm2_kernel<<<g2, 256>>>(W2, b2);

    combine_kernel<<<(B_TOK * ODIM / 4) / 256, 256>>>(out);
}

// round 3
// speedup vs baseline: 1.9873x; 1.9873x over previous
#include <cuda_runtime.h>
#include <cuda_bf16.h>
#include <cstdint>

#define B_TOK 8192
#define DDIM  1024
#define HDIM  2048
#define ODIM  1024
#define NEXP  8

#define MT 128
#define NT 128
#define KC 64

// ---------------- scratch (device globals: allocation-free rule) -------------
__device__ int   g_count[NEXP];
__device__ int   g_list[NEXP * B_TOK];     // entry = token*2 + slot
__device__ float g_wlist[NEXP * B_TOK];
__device__ __nv_bfloat16 g_W1t_hi[(size_t)NEXP * HDIM * DDIM];  // [E][H][D]
__device__ __nv_bfloat16 g_W1t_lo[(size_t)NEXP * HDIM * DDIM];
__device__ __nv_bfloat16 g_W2t_hi[(size_t)NEXP * ODIM * HDIM];  // [E][O][H]
__device__ __nv_bfloat16 g_W2t_lo[(size_t)NEXP * ODIM * HDIM];
__device__ __nv_bfloat16 g_h_hi[(size_t)2 * B_TOK * HDIM];      // [16384][H]
__device__ __nv_bfloat16 g_h_lo[(size_t)2 * B_TOK * HDIM];
__device__ float g_part[(size_t)2 * B_TOK * ODIM];

// ---------------- helpers ----------------------------------------------------
__device__ __forceinline__ uint32_t smem_u32(const void* p) {
    uint32_t a;
    asm("{ .reg .u64 t; cvta.to.shared.u64 t, %1; cvt.u32.u64 %0, t; }"
        : "=r"(a) : "l"(p));
    return a;
}
#define SW(o) ((o) ^ (((o) >> 3) & 0x70))

__device__ __forceinline__ void ldsm4(uint32_t* r, uint32_t a) {
    asm volatile("ldmatrix.sync.aligned.m8n8.x4.shared.b16 {%0,%1,%2,%3}, [%4];"
        : "=r"(r[0]), "=r"(r[1]), "=r"(r[2]), "=r"(r[3]) : "r"(a));
}
__device__ __forceinline__ void mma16816(float* c, const uint32_t* a, const uint32_t* b) {
    asm volatile("mma.sync.aligned.m16n8k16.row.col.f32.bf16.bf16.f32 "
        "{%0,%1,%2,%3}, {%4,%5,%6,%7}, {%8,%9}, {%0,%1,%2,%3};"
        : "+f"(c[0]), "+f"(c[1]), "+f"(c[2]), "+f"(c[3])
        : "r"(a[0]), "r"(a[1]), "r"(a[2]), "r"(a[3]), "r"(b[0]), "r"(b[1]));
}
#define CP16(dst, src) \
    asm volatile("cp.async.cg.shared.global [%0], [%1], 16;" :: "r"(dst), "l"(src))
#define CP_COMMIT() asm volatile("cp.async.commit_group;" ::: "memory")
#define CP_WAIT1()  asm volatile("cp.async.wait_group 1;" ::: "memory")
#define CP_WAIT0()  asm volatile("cp.async.wait_group 0;" ::: "memory")

__device__ __forceinline__ void bsplit(float v, __nv_bfloat16& h, __nv_bfloat16& l) {
    h = __float2bfloat16_rn(v);
    l = __float2bfloat16_rn(v - __bfloat162float(h));
}
__device__ __forceinline__ uint32_t pkb(__nv_bfloat16 a, __nv_bfloat16 b) {
    return (uint32_t)__bfloat16_as_ushort(a) | ((uint32_t)__bfloat16_as_ushort(b) << 16);
}

// ---------------- SMEM layout ------------------------------------------------
// [0,512)    sEnt      [512,1024) sW       [1024,1536) sBias
// [2048, 2048+16K)  AH   [+16K, +32K) AL     (single-buffered)
// [34816, +32K) Bbuf0 (BH|BL)   [67584, +32K) Bbuf1
#define OFF_ENT  0
#define OFF_W    512
#define OFF_BIAS 1024
#define OFF_A    2048
#define OFF_B    34816
#define PLANE    16384
#define SMEM_BYTES (OFF_B + 2 * 32768)   // 100352

// ============================ gating =========================================
__global__ void zero_counts_kernel() {
    if (threadIdx.x < NEXP) g_count[threadIdx.x] = 0;
}

__global__ void gate_kernel(const float* __restrict__ x,
                            const float* __restrict__ Wg,
                            const float* __restrict__ bg) {
    int gw   = (blockIdx.x * blockDim.x + threadIdx.x) >> 5;
    int lane = threadIdx.x & 31;
    if (gw >= B_TOK) return;
    const float* xr = x + (size_t)gw * DDIM;
    float acc[NEXP];
#pragma unroll
    for (int e = 0; e < NEXP; e++) acc[e] = 0.f;
    for (int d = lane; d < DDIM; d += 32) {
        float xv = xr[d];
        const float4* w4 = reinterpret_cast<const float4*>(Wg + (size_t)d * NEXP);
        float4 w0 = w4[0], w1 = w4[1];
        acc[0] += xv * w0.x; acc[1] += xv * w0.y;
        acc[2] += xv * w0.z; acc[3] += xv * w0.w;
        acc[4] += xv * w1.x; acc[5] += xv * w1.y;
        acc[6] += xv * w1.z; acc[7] += xv * w1.w;
    }
#pragma unroll
    for (int off = 16; off; off >>= 1)
#pragma unroll
        for (int e = 0; e < NEXP; e++)
            acc[e] += __shfl_xor_sync(0xFFFFFFFFu, acc[e], off);
    if (lane == 0) {
        float s[NEXP];
#pragma unroll
        for (int e = 0; e < NEXP; e++) s[e] = acc[e] + bg[e];
        float M = s[0];
#pragma unroll
        for (int e = 1; e < NEXP; e++) M = fmaxf(M, s[e]);
        float p[NEXP], Z = 0.f;
#pragma unroll
        for (int e = 0; e < NEXP; e++) { p[e] = expf(s[e] - M); Z += p[e]; }
        int i1 = 0;
#pragma unroll
        for (int e = 1; e < NEXP; e++) if (s[e] > s[i1]) i1 = e;
        int i2 = -1;
#pragma unroll
        for (int e = 0; e < NEXP; e++)
            if (e != i1 && (i2 < 0 || s[e] > s[i2])) i2 = e;
        float denom = p[i1] + p[i2] + 1e-8f * Z;
        float w1 = p[i1] / denom;
        float w2 = p[i2] / denom;
        int pos1 = atomicAdd(&g_count[i1], 1);
        g_list[i1 * B_TOK + pos1]  = gw * 2 + 0;
        g_wlist[i1 * B_TOK + pos1] = w1;
        int pos2 = atomicAdd(&g_count[i2], 1);
        g_list[i2 * B_TOK + pos2]  = gw * 2 + 1;
        g_wlist[i2 * B_TOK + pos2] = w2;
    }
}

// ============ weight transpose + bf16 hi/lo split ============================
__global__ void convW1_kernel(const float* __restrict__ W1) {
    __shared__ float ts[32][33];
    int e = blockIdx.z;
    int h0 = blockIdx.x * 32, d0 = blockIdx.y * 32;
    int tx = threadIdx.x, ty = threadIdx.y;
    const float* src = W1 + ((size_t)e * DDIM + d0) * HDIM + h0;
#pragma unroll
    for (int j = 0; j < 4; j++)
        ts[ty + 8 * j][tx] = src[(size_t)(ty + 8 * j) * HDIM + tx];
    __syncthreads();
#pragma unroll
    for (int j = 0; j < 4; j++) {
        int h = h0 + ty + 8 * j;
        float v = ts[tx][ty + 8 * j];
        __nv_bfloat16 hi, lo; bsplit(v, hi, lo);
        size_t idx = ((size_t)e * HDIM + h) * DDIM + d0 + tx;
        g_W1t_hi[idx] = hi; g_W1t_lo[idx] = lo;
    }
}

__global__ void convW2_kernel(const float* __restrict__ W2) {
    __shared__ float ts[32][33];
    int e = blockIdx.z;
    int o0 = blockIdx.x * 32, h0 = blockIdx.y * 32;
    int tx = threadIdx.x, ty = threadIdx.y;
    const float* src = W2 + ((size_t)e * HDIM + h0) * ODIM + o0;
#pragma unroll
    for (int j = 0; j < 4; j++)
        ts[ty + 8 * j][tx] = src[(size_t)(ty + 8 * j) * ODIM + tx];
    __syncthreads();
#pragma unroll
    for (int j = 0; j < 4; j++) {
        int o = o0 + ty + 8 * j;
        float v = ts[tx][ty + 8 * j];
        __nv_bfloat16 hi, lo; bsplit(v, hi, lo);
        size_t idx = ((size_t)e * ODIM + o) * HDIM + h0 + tx;
        g_W2t_hi[idx] = hi; g_W2t_lo[idx] = lo;
    }
}

// ============================ GEMM cores =====================================
// 8 warps: warp tile 64x32 (mi 0..3 of m16, ni 0..3 of n8), bf16x3 via mma.sync.
struct Frag { float acc[4][4][4]; };

__device__ __forceinline__ void mma_compute(uint32_t sb, int bsel,
                                            int rA, int aSel, int rB, int bSel,
                                            float acc[4][4][4]) {
    const uint32_t Abase = sb + OFF_A;
    const uint32_t Bbase = sb + OFF_B + (uint32_t)bsel * 32768u;
#pragma unroll
    for (int k16 = 0; k16 < 4; k16++) {
        const uint32_t kb = k16 * 32;
        uint32_t bhf[2][4], blf[2][4];
#pragma unroll
        for (int nip = 0; nip < 2; nip++) {
            uint32_t off = SW((uint32_t)(rB + nip * 16) * 128 + kb + bSel * 16);
            ldsm4(bhf[nip], Bbase + off);
            ldsm4(blf[nip], Bbase + PLANE + off);
        }
#pragma unroll
        for (int mi = 0; mi < 4; mi++) {
            uint32_t offA = SW((uint32_t)(rA + mi * 16) * 128 + kb + aSel * 16);
            uint32_t ah[4], al[4];
            ldsm4(ah, Abase + offA);
            ldsm4(al, Abase + PLANE + offA);
#pragma unroll
            for (int ni = 0; ni < 4; ni++) {
                const uint32_t* bh = &bhf[ni >> 1][(ni & 1) * 2];
                const uint32_t* bl = &blf[ni >> 1][(ni & 1) * 2];
                mma16816(acc[mi][ni], ah, bh);
                mma16816(acc[mi][ni], al, bh);
                mma16816(acc[mi][ni], ah, bl);
            }
        }
    }
}

// ---------------- GEMM1: h = relu(x_g @ W1t^T + b1) --------------------------
__global__ __launch_bounds__(256)
void gemm1_mma(const float* __restrict__ x, const float* __restrict__ b1) {
    const int e = blockIdx.z;
    const int count = g_count[e];
    const int r0 = blockIdx.y * MT;
    if (r0 >= count) return;
    const int n0 = blockIdx.x * NT;

    extern __shared__ char smem[];
    const uint32_t sb = smem_u32(smem);
    const int t = threadIdx.x, wid = t >> 5, lane = t & 31;

    int*   sEnt  = (int*)(smem + OFF_ENT);
    float* sBias = (float*)(smem + OFF_BIAS);
    if (t < 128) {
        int pos = r0 + t;
        sEnt[t]  = (pos < count) ? g_list[e * B_TOK + pos] : -1;
        sBias[t] = b1[(size_t)e * HDIM + n0 + t];
    }
    __syncthreads();

    // A gather (fp32 -> split at store): thread t covers row t/2, half (t&1)
    const int r = t >> 1;
    const int ent = sEnt[r];
    const float* aRow = x + (size_t)((ent < 0 ? 0 : ent) >> 1) * DDIM + (t & 1) * 32;
    const uint32_t rowOff = (uint32_t)r * 128 + (t & 1) * 64;

    // B cp.async: thread t covers rows (t>>3)+32i, 16B col (t&7)
    const int brow = t >> 3, bcol = t & 7;
    uint32_t bdst[4];
#pragma unroll
    for (int i = 0; i < 4; i++) bdst[i] = SW((uint32_t)(brow + 32 * i) * 128 + bcol * 16);
    const __nv_bfloat16* bsrcH = g_W1t_hi + ((size_t)e * HDIM + n0 + brow) * DDIM + bcol * 8;
    const __nv_bfloat16* bsrcL = g_W1t_lo + ((size_t)e * HDIM + n0 + brow) * DDIM + bcol * 8;

    const int wm = (wid >> 2) * 64, wn = (wid & 3) * 32;
    const int rA = wm + (lane & 7) + ((lane >> 3) & 1) * 8, aSel = (lane >> 4) & 1;
    const int rB = wn + (lane & 7) + ((lane >> 4) & 1) * 8, bSel = (lane >> 3) & 1;

    float acc[4][4][4];
#pragma unroll
    for (int a = 0; a < 4; a++)
#pragma unroll
        for (int bq = 0; bq < 4; bq++)
#pragma unroll
            for (int c = 0; c < 4; c++) acc[a][bq][c] = 0.f;

    const int NS = DDIM / KC;  // 16
    // prologue
    float4 va[8];
#pragma unroll
    for (int i = 0; i < 8; i++) va[i] = *(const float4*)(aRow + 4 * i);
    {
        uint32_t Bb = sb + OFF_B;
#pragma unroll
        for (int i = 0; i < 4; i++) {
            CP16(Bb + bdst[i],         bsrcH + (size_t)32 * i * DDIM);
            CP16(Bb + PLANE + bdst[i], bsrcL + (size_t)32 * i * DDIM);
        }
        CP_COMMIT();
    }

    for (int kt = 0; kt < NS; kt++) {
        const int bsel = kt & 1;
        __syncthreads();
        // store A (split)
        {
            char* dAH = smem + OFF_A;
            char* dAL = smem + OFF_A + PLANE;
#pragma unroll
            for (int i = 0; i < 8; i++) {
                __nv_bfloat16 h0, h1, h2, h3, l0, l1, l2, l3;
                bsplit(va[i].x, h0, l0); bsplit(va[i].y, h1, l1);
                bsplit(va[i].z, h2, l2); bsplit(va[i].w, h3, l3);
                uint32_t so = SW(rowOff + 8 * i);
                *(uint2*)(dAH + so) = make_uint2(pkb(h0, h1), pkb(h2, h3));
                *(uint2*)(dAL + so) = make_uint2(pkb(l0, l1), pkb(l2, l3));
            }
        }
        if (kt + 1 < NS) {
            uint32_t Bb = sb + OFF_B + (uint32_t)((kt + 1) & 1) * 32768u;
            const size_t ko = (size_t)(kt + 1) * KC;
#pragma unroll
            for (int i = 0; i < 4; i++) {
                CP16(Bb + bdst[i],         bsrcH + (size_t)32 * i * DDIM + ko);
                CP16(Bb + PLANE + bdst[i], bsrcL + (size_t)32 * i * DDIM + ko);
            }
            CP_COMMIT();
            CP_WAIT1();
        } else {
            CP_WAIT0();
        }
        __syncthreads();
        // prefetch next A
        const int ktn = (kt + 1 < NS) ? kt + 1 : kt;
#pragma unroll
        for (int i = 0; i < 8; i++)
            va[i] = *(const float4*)(aRow + (size_t)ktn * KC + 4 * i);

        mma_compute(sb, bsel, rA, aSel, rB, bSel, acc);
    }

    // epilogue: bias + relu, split to g_h planes
    const int crow = lane >> 2, ccol = (lane & 3) * 2;
#pragma unroll
    for (int mi = 0; mi < 4; mi++)
#pragma unroll
        for (int h = 0; h < 2; h++) {
            const int ml = wm + mi * 16 + crow + h * 8;
            const int entm = sEnt[ml];
            if (entm < 0) continue;
            __nv_bfloat16* ohi = g_h_hi + (size_t)entm * HDIM + n0;
            __nv_bfloat16* olo = g_h_lo + (size_t)entm * HDIM + n0;
#pragma unroll
            for (int ni = 0; ni < 4; ni++) {
                const int tn = wn + ni * 8 + ccol;
                float v0 = fmaxf(acc[mi][ni][h * 2 + 0] + sBias[tn], 0.f);
                float v1 = fmaxf(acc[mi][ni][h * 2 + 1] + sBias[tn + 1], 0.f);
                __nv_bfloat16 h0, l0, h1, l1;
                bsplit(v0, h0, l0); bsplit(v1, h1, l1);
                *(uint32_t*)(ohi + tn) = pkb(h0, h1);
                *(uint32_t*)(olo + tn) = pkb(l0, l1);
            }
        }
}

// ---------------- GEMM2: part = w * (h @ W2t^T + b2) -------------------------
__global__ __launch_bounds__(256)
void gemm2_mma(const float* __restrict__ b2) {
    const int e = blockIdx.z;
    const int count = g_count[e];
    const int r0 = blockIdx.y * MT;
    if (r0 >= count) return;
    const int n0 = blockIdx.x * NT;

    extern __shared__ char smem[];
    const uint32_t sb = smem_u32(smem);
    const int t = threadIdx.x, wid = t >> 5, lane = t & 31;

    int*   sEnt  = (int*)(smem + OFF_ENT);
    float* sW    = (float*)(smem + OFF_W);
    float* sBias = (float*)(smem + OFF_BIAS);
    if (t < 128) {
        int pos = r0 + t;
        bool ok = (pos < count);
        sEnt[t]  = ok ? g_list[e * B_TOK + pos] : -1;
        sW[t]    = ok ? g_wlist[e * B_TOK + pos] : 0.f;
        sBias[t] = b2[(size_t)e * ODIM + n0 + t];
    }
    __syncthreads();

    const int r = t >> 1;
    const int ent = sEnt[r];
    const size_t arow = (size_t)(ent < 0 ? 0 : ent) * HDIM + (t & 1) * 32;
    const __nv_bfloat16* aRowH = g_h_hi + arow;
    const __nv_bfloat16* aRowL = g_h_lo + arow;
    const uint32_t rowOff = (uint32_t)r * 128 + (t & 1) * 64;

    const int brow = t >> 3, bcol = t & 7;
    uint32_t bdst[4];
#pragma unroll
    for (int i = 0; i < 4; i++) bdst[i] = SW((uint32_t)(brow + 32 * i) * 128 + bcol * 16);
    const __nv_bfloat16* bsrcH = g_W2t_hi + ((size_t)e * ODIM + n0 + brow) * HDIM + bcol * 8;
    const __nv_bfloat16* bsrcL = g_W2t_lo + ((size_t)e * ODIM + n0 + brow) * HDIM + bcol * 8;

    const int wm = (wid >> 2) * 64, wn = (wid & 3) * 32;
    const int rA = wm + (lane & 7) + ((lane >> 3) & 1) * 8, aSel = (lane >> 4) & 1;
    const int rB = wn + (lane & 7) + ((lane >> 4) & 1) * 8, bSel = (lane >> 3) & 1;

    float acc[4][4][4];
#pragma unroll
    for (int a = 0; a < 4; a++)
#pragma unroll
        for (int bq = 0; bq < 4; bq++)
#pragma unroll
            for (int c = 0; c < 4; c++) acc[a][bq][c] = 0.f;

    const int NS = HDIM / KC;  // 32
    uint4 vah[4], valr[4];
#pragma unroll
    for (int i = 0; i < 4; i++) {
        vah[i]  = ((const uint4*)aRowH)[i];
        valr[i] = ((const uint4*)aRowL)[i];
    }
    {
        uint32_t Bb = sb + OFF_B;
#pragma unroll
        for (int i = 0; i < 4; i++) {
            CP16(Bb + bdst[i],         bsrcH + (size_t)32 * i * HDIM);
            CP16(Bb + PLANE + bdst[i], bsrcL + (size_t)32 * i * HDIM);
        }
        CP_COMMIT();
    }

    for (int kt = 0; kt < NS; kt++) {
        const int bsel = kt & 1;
        __syncthreads();
        {
            char* dAH = smem + OFF_A;
            char* dAL = smem + OFF_A + PLANE;
#pragma unroll
            for (int i = 0; i < 4; i++) {
                uint32_t so = SW(rowOff + 16 * i);
                *(uint4*)(dAH + so) = vah[i];
                *(uint4*)(dAL + so) = valr[i];
            }
        }
        if (kt + 1 < NS) {
            uint32_t Bb = sb + OFF_B + (uint32_t)((kt + 1) & 1) * 32768u;
            const size_t ko = (size_t)(kt + 1) * KC;
#pragma unroll
            for (int i = 0; i < 4; i++) {
                CP16(Bb + bdst[i],         bsrcH + (size_t)32 * i * HDIM + ko);
                CP16(Bb + PLANE + bdst[i], bsrcL + (size_t)32 * i * HDIM + ko);
            }
            CP_COMMIT();
            CP_WAIT1();
        } else {
            CP_WAIT0();
        }
        __syncthreads();
        const int ktn = (kt + 1 < NS) ? kt + 1 : kt;
#pragma unroll
        for (int i = 0; i < 4; i++) {
            vah[i]  = ((const uint4*)(aRowH + (size_t)ktn * KC))[i];
            valr[i] = ((const uint4*)(aRowL + (size_t)ktn * KC))[i];
        }

        mma_compute(sb, bsel, rA, aSel, rB, bSel, acc);
    }

    // epilogue: (acc + bias) * weight -> g_part
    const int crow = lane >> 2, ccol = (lane & 3) * 2;
#pragma unroll
    for (int mi = 0; mi < 4; mi++)
#pragma unroll
        for (int h = 0; h < 2; h++) {
            const int ml = wm + mi * 16 + crow + h * 8;
            const int entm = sEnt[ml];
            if (entm < 0) continue;
            const float wt = sW[ml];
            float* op = g_part + (size_t)entm * ODIM + n0;
#pragma unroll
            for (int ni = 0; ni < 4; ni++) {
                const int tn = wn + ni * 8 + ccol;
                float2 v;
                v.x = (acc[mi][ni][h * 2 + 0] + sBias[tn]) * wt;
                v.y = (acc[mi][ni][h * 2 + 1] + sBias[tn + 1]) * wt;
                *(float2*)(op + tn) = v;
            }
        }
}

// ============================ combine ========================================
__global__ void combine_kernel(float* __restrict__ out) {
    int idx = blockIdx.x * blockDim.x + threadIdx.x;
    const int OW = ODIM / 4;
    int b  = idx / OW;
    int o4 = idx - b * OW;
    const float4* p = reinterpret_cast<const float4*>(g_part);
    float4 u = p[(size_t)(2 * b) * OW + o4];
    float4 v = p[(size_t)(2 * b + 1) * OW + o4];
    float4 r;
    r.x = u.x + v.x; r.y = u.y + v.y; r.z = u.z + v.z; r.w = u.w + v.w;
    reinterpret_cast<float4*>(out)[idx] = r;
}

// ============================ launch =========================================
extern "C" void kernel_launch(void* const* d_in, const int* in_sizes, int n_in,
                              void* d_out, int out_size) {
    const float* x  = (const float*)d_in[0];
    const float* Wg = (const float*)d_in[1];
    const float* bg = (const float*)d_in[2];
    const float* W1 = (const float*)d_in[3];
    const float* b1 = (const float*)d_in[4];
    const float* W2 = (const float*)d_in[5];
    const float* b2 = (const float*)d_in[6];
    float* out = (float*)d_out;

    static int smem_set = 0;
    if (!smem_set) {
        cudaFuncSetAttribute(gemm1_mma, cudaFuncAttributeMaxDynamicSharedMemorySize, SMEM_BYTES);
        cudaFuncSetAttribute(gemm2_mma, cudaFuncAttributeMaxDynamicSharedMemorySize, SMEM_BYTES);
        smem_set = 1;
    }

    zero_counts_kernel<<<1, 32>>>();
    gate_kernel<<<B_TOK / 8, 256>>>(x, Wg, bg);

    convW1_kernel<<<dim3(HDIM / 32, DDIM / 32, NEXP), dim3(32, 8)>>>(W1);
    convW2_kernel<<<dim3(ODIM / 32, HDIM / 32, NEXP), dim3(32, 8)>>>(W2);

    gemm1_mma<<<dim3(HDIM / NT, B_TOK / MT, NEXP), 256, SMEM_BYTES>>>(x, b1);
    gemm2_mma<<<dim3(ODIM / NT, B_TOK / MT, NEXP), 256, SMEM_BYTES>>>(b2);

    combine_kernel<<<(B_TOK * ODIM / 4) / 256, 256>>>(out);
}

// round 5
// speedup vs baseline: 2.1478x; 1.0807x over previous
#include <cuda_runtime.h>
#include <cuda_bf16.h>
#include <cstdint>

#define B_TOK 8192
#define DDIM  1024
#define HDIM  2048
#define ODIM  1024
#define NEXP  8

#define MT 128
#define NT 128
#define KC 64

// ---------------- scratch (device globals: allocation-free rule) -------------
__device__ int   g_count[NEXP];
__device__ int   g_list[NEXP * B_TOK];     // entry = token*2 + slot
__device__ float g_wlist[NEXP * B_TOK];
__device__ alignas(128) __nv_bfloat16 g_x_hi[(size_t)B_TOK * DDIM];
__device__ alignas(128) __nv_bfloat16 g_x_lo[(size_t)B_TOK * DDIM];
__device__ alignas(128) __nv_bfloat16 g_W1t_hi[(size_t)NEXP * HDIM * DDIM];  // [E][H][D]
__device__ alignas(128) __nv_bfloat16 g_W1t_lo[(size_t)NEXP * HDIM * DDIM];
__device__ alignas(128) __nv_bfloat16 g_W2t_hi[(size_t)NEXP * ODIM * HDIM];  // [E][O][H]
__device__ alignas(128) __nv_bfloat16 g_W2t_lo[(size_t)NEXP * ODIM * HDIM];
__device__ alignas(128) __nv_bfloat16 g_h_hi[(size_t)2 * B_TOK * HDIM];      // [16384][H]
__device__ alignas(128) __nv_bfloat16 g_h_lo[(size_t)2 * B_TOK * HDIM];
__device__ float g_part[(size_t)2 * B_TOK * ODIM];

// ---------------- helpers ----------------------------------------------------
__device__ __forceinline__ uint32_t smem_u32(const void* p) {
    uint32_t a;
    asm("{ .reg .u64 t; cvta.to.shared.u64 t, %1; cvt.u32.u64 %0, t; }"
        : "=r"(a) : "l"(p));
    return a;
}
#define SW(o) ((o) ^ (((o) >> 3) & 0x70))

__device__ __forceinline__ void ldsm4(uint32_t* r, uint32_t a) {
    asm volatile("ldmatrix.sync.aligned.m8n8.x4.shared.b16 {%0,%1,%2,%3}, [%4];"
        : "=r"(r[0]), "=r"(r[1]), "=r"(r[2]), "=r"(r[3]) : "r"(a));
}
__device__ __forceinline__ void mma16816(float* c, const uint32_t* a, const uint32_t* b) {
    asm volatile("mma.sync.aligned.m16n8k16.row.col.f32.bf16.bf16.f32 "
        "{%0,%1,%2,%3}, {%4,%5,%6,%7}, {%8,%9}, {%0,%1,%2,%3};"
        : "+f"(c[0]), "+f"(c[1]), "+f"(c[2]), "+f"(c[3])
        : "r"(a[0]), "r"(a[1]), "r"(a[2]), "r"(a[3]), "r"(b[0]), "r"(b[1]));
}
#define CP16(dst, src) \
    asm volatile("cp.async.cg.shared.global [%0], [%1], 16;" :: "r"(dst), "l"(src))
#define CP_COMMIT() asm volatile("cp.async.commit_group;" ::: "memory")
#define CP_WAIT1()  asm volatile("cp.async.wait_group 1;" ::: "memory")
#define CP_WAIT0()  asm volatile("cp.async.wait_group 0;" ::: "memory")

__device__ __forceinline__ void bsplit(float v, __nv_bfloat16& h, __nv_bfloat16& l) {
    h = __float2bfloat16_rn(v);
    l = __float2bfloat16_rn(v - __bfloat162float(h));
}
__device__ __forceinline__ uint32_t pkb(__nv_bfloat16 a, __nv_bfloat16 b) {
    return (uint32_t)__bfloat16_as_ushort(a) | ((uint32_t)__bfloat16_as_ushort(b) << 16);
}

// ---------------- SMEM layout ------------------------------------------------
// [0,512) sEnt  [512,1024) sW  [1024,1536) sBias
// [2048, 2048 + 3*64K) : 3 pipeline stages, each [AH|AL|BH|BL] x 16KB
#define OFF_ENT  0
#define OFF_W    512
#define OFF_BIAS 1024
#define OFF_T    2048
#define PLANE    16384
#define STAGE    65536
#define SMEM_BYTES (OFF_T + 3 * STAGE)   // 198656

// ============================ gating =========================================
__global__ void zero_counts_kernel() {
    if (threadIdx.x < NEXP) g_count[threadIdx.x] = 0;
}

__global__ void gate_kernel(const float* __restrict__ x,
                            const float* __restrict__ Wg,
                            const float* __restrict__ bg) {
    int gw   = (blockIdx.x * blockDim.x + threadIdx.x) >> 5;
    int lane = threadIdx.x & 31;
    if (gw >= B_TOK) return;
    const float* xr = x + (size_t)gw * DDIM;
    float acc[NEXP];
#pragma unroll
    for (int e = 0; e < NEXP; e++) acc[e] = 0.f;
    for (int d = lane; d < DDIM; d += 32) {
        float xv = xr[d];
        const float4* w4 = reinterpret_cast<const float4*>(Wg + (size_t)d * NEXP);
        float4 w0 = w4[0], w1 = w4[1];
        acc[0] += xv * w0.x; acc[1] += xv * w0.y;
        acc[2] += xv * w0.z; acc[3] += xv * w0.w;
        acc[4] += xv * w1.x; acc[5] += xv * w1.y;
        acc[6] += xv * w1.z; acc[7] += xv * w1.w;
    }
#pragma unroll
    for (int off = 16; off; off >>= 1)
#pragma unroll
        for (int e = 0; e < NEXP; e++)
            acc[e] += __shfl_xor_sync(0xFFFFFFFFu, acc[e], off);
    if (lane == 0) {
        float s[NEXP];
#pragma unroll
        for (int e = 0; e < NEXP; e++) s[e] = acc[e] + bg[e];
        float M = s[0];
#pragma unroll
        for (int e = 1; e < NEXP; e++) M = fmaxf(M, s[e]);
        float p[NEXP], Z = 0.f;
#pragma unroll
        for (int e = 0; e < NEXP; e++) { p[e] = expf(s[e] - M); Z += p[e]; }
        int i1 = 0;
#pragma unroll
        for (int e = 1; e < NEXP; e++) if (s[e] > s[i1]) i1 = e;
        int i2 = -1;
#pragma unroll
        for (int e = 0; e < NEXP; e++)
            if (e != i1 && (i2 < 0 || s[e] > s[i2])) i2 = e;
        float denom = p[i1] + p[i2] + 1e-8f * Z;
        float w1 = p[i1] / denom;
        float w2 = p[i2] / denom;
        int pos1 = atomicAdd(&g_count[i1], 1);
        g_list[i1 * B_TOK + pos1]  = gw * 2 + 0;
        g_wlist[i1 * B_TOK + pos1] = w1;
        int pos2 = atomicAdd(&g_count[i2], 1);
        g_list[i2 * B_TOK + pos2]  = gw * 2 + 1;
        g_wlist[i2 * B_TOK + pos2] = w2;
    }
}

// ============ conversions: x split, weight transpose+split ===================
__global__ void convX_kernel(const float* __restrict__ x) {
    size_t idx = (size_t)blockIdx.x * blockDim.x + threadIdx.x;  // over B*D/4
    float4 v = reinterpret_cast<const float4*>(x)[idx];
    __nv_bfloat16 h0, h1, h2, h3, l0, l1, l2, l3;
    bsplit(v.x, h0, l0); bsplit(v.y, h1, l1);
    bsplit(v.z, h2, l2); bsplit(v.w, h3, l3);
    reinterpret_cast<uint2*>(g_x_hi)[idx] = make_uint2(pkb(h0, h1), pkb(h2, h3));
    reinterpret_cast<uint2*>(g_x_lo)[idx] = make_uint2(pkb(l0, l1), pkb(l2, l3));
}

__global__ void convW1_kernel(const float* __restrict__ W1) {
    __shared__ float ts[32][33];
    int e = blockIdx.z;
    int h0 = blockIdx.x * 32, d0 = blockIdx.y * 32;
    int tx = threadIdx.x, ty = threadIdx.y;
    const float* src = W1 + ((size_t)e * DDIM + d0) * HDIM + h0;
#pragma unroll
    for (int j = 0; j < 4; j++)
        ts[ty + 8 * j][tx] = src[(size_t)(ty + 8 * j) * HDIM + tx];
    __syncthreads();
#pragma unroll
    for (int j = 0; j < 4; j++) {
        int h = h0 + ty + 8 * j;
        float v = ts[tx][ty + 8 * j];
        __nv_bfloat16 hi, lo; bsplit(v, hi, lo);
        size_t idx = ((size_t)e * HDIM + h) * DDIM + d0 + tx;
        g_W1t_hi[idx] = hi; g_W1t_lo[idx] = lo;
    }
}

__global__ void convW2_kernel(const float* __restrict__ W2) {
    __shared__ float ts[32][33];
    int e = blockIdx.z;
    int o0 = blockIdx.x * 32, h0 = blockIdx.y * 32;
    int tx = threadIdx.x, ty = threadIdx.y;
    const float* src = W2 + ((size_t)e * HDIM + h0) * ODIM + o0;
#pragma unroll
    for (int j = 0; j < 4; j++)
        ts[ty + 8 * j][tx] = src[(size_t)(ty + 8 * j) * ODIM + tx];
    __syncthreads();
#pragma unroll
    for (int j = 0; j < 4; j++) {
        int o = o0 + ty + 8 * j;
        float v = ts[tx][ty + 8 * j];
        __nv_bfloat16 hi, lo; bsplit(v, hi, lo);
        size_t idx = ((size_t)e * ODIM + o) * HDIM + h0 + tx;
        g_W2t_hi[idx] = hi; g_W2t_lo[idx] = lo;
    }
}

// ============================ GEMM core ======================================
// 8 warps; warp tile 64x32; pass-outer ordering to break HMMA dependency chains
__device__ __forceinline__ void mma_stage(uint32_t sb, int st,
                                          int rA, int aSel, int rB, int bSel,
                                          float acc[4][4][4]) {
    const uint32_t AH = sb + OFF_T + (uint32_t)st * STAGE;
    const uint32_t AL = AH + PLANE;
    const uint32_t BH = AH + 2 * PLANE;
    const uint32_t BL = AH + 3 * PLANE;
#pragma unroll
    for (int k16 = 0; k16 < 4; k16++) {
        const uint32_t kb = k16 * 32;
        uint32_t ah[4][4], al[4][4], bh[2][4], bl[2][4];
#pragma unroll
        for (int nip = 0; nip < 2; nip++) {
            uint32_t off = SW((uint32_t)(rB + nip * 16) * 128 + kb + bSel * 16);
            ldsm4(bh[nip], BH + off);
            ldsm4(bl[nip], BL + off);
        }
#pragma unroll
        for (int mi = 0; mi < 4; mi++) {
            uint32_t off = SW((uint32_t)(rA + mi * 16) * 128 + kb + aSel * 16);
            ldsm4(ah[mi], AH + off);
            ldsm4(al[mi], AL + off);
        }
        // pass 1: Ah*Bh
#pragma unroll
        for (int mi = 0; mi < 4; mi++)
#pragma unroll
            for (int ni = 0; ni < 4; ni++)
                mma16816(acc[mi][ni], ah[mi], &bh[ni >> 1][(ni & 1) * 2]);
        // pass 2: Al*Bh
#pragma unroll
        for (int mi = 0; mi < 4; mi++)
#pragma unroll
            for (int ni = 0; ni < 4; ni++)
                mma16816(acc[mi][ni], al[mi], &bh[ni >> 1][(ni & 1) * 2]);
        // pass 3: Ah*Bl
#pragma unroll
        for (int mi = 0; mi < 4; mi++)
#pragma unroll
            for (int ni = 0; ni < 4; ni++)
                mma16816(acc[mi][ni], ah[mi], &bl[ni >> 1][(ni & 1) * 2]);
    }
}

// ---------------- GEMM1: h = relu(x_g @ W1t^T + b1) --------------------------
__global__ __launch_bounds__(256)
void gemm1_mma(const float* __restrict__ b1) {
    const int e = blockIdx.z;
    const int count = g_count[e];
    const int r0 = blockIdx.y * MT;
    if (r0 >= count) return;
    const int n0 = blockIdx.x * NT;

    extern __shared__ char smem[];
    const uint32_t sb = smem_u32(smem);
    const int t = threadIdx.x, wid = t >> 5, lane = t & 31;

    int*   sEnt  = (int*)(smem + OFF_ENT);
    float* sBias = (float*)(smem + OFF_BIAS);
    if (t < 128) {
        int pos = r0 + t;
        sEnt[t]  = (pos < count) ? g_list[e * B_TOK + pos] : -1;
        sBias[t] = b1[(size_t)e * HDIM + n0 + t];
    }
    __syncthreads();

    // per-thread copy coords: row r = t>>1, 64B half (t&1)
    const int r = t >> 1;
    const int half = t & 1;
    const int ent = sEnt[r];
    const int tok = (ent < 0 ? 0 : ent) >> 1;
    const __nv_bfloat16* aH = g_x_hi + (size_t)tok * DDIM + half * 32;
    const __nv_bfloat16* aL = g_x_lo + (size_t)tok * DDIM + half * 32;
    const __nv_bfloat16* bH = g_W1t_hi + ((size_t)e * HDIM + n0 + r) * DDIM + half * 32;
    const __nv_bfloat16* bL = g_W1t_lo + ((size_t)e * HDIM + n0 + r) * DDIM + half * 32;
    uint32_t swo[4];
    const uint32_t rowOff = (uint32_t)r * 128 + half * 64;
#pragma unroll
    for (int i = 0; i < 4; i++) swo[i] = SW(rowOff + 16 * i);

    auto issue = [&](int kt) {
        uint32_t dst = sb + OFF_T + (uint32_t)(kt % 3) * STAGE;
        const size_t ko = (size_t)kt * KC;
#pragma unroll
        for (int i = 0; i < 4; i++) {
            uint32_t d = dst + swo[i];
            CP16(d,             aH + ko + i * 8);
            CP16(d + PLANE,     aL + ko + i * 8);
            CP16(d + 2 * PLANE, bH + ko + i * 8);
            CP16(d + 3 * PLANE, bL + ko + i * 8);
        }
        CP_COMMIT();
    };

    const int wm = (wid >> 2) * 64, wn = (wid & 3) * 32;
    const int rA = wm + (lane & 7) + ((lane >> 3) & 1) * 8, aSel = (lane >> 4) & 1;
    const int rB = wn + (lane & 7) + ((lane >> 4) & 1) * 8, bSel = (lane >> 3) & 1;

    float acc[4][4][4];
#pragma unroll
    for (int a = 0; a < 4; a++)
#pragma unroll
        for (int bq = 0; bq < 4; bq++)
#pragma unroll
            for (int c = 0; c < 4; c++) acc[a][bq][c] = 0.f;

    const int NS = DDIM / KC;  // 16
    issue(0); issue(1);
    for (int kt = 0; kt < NS; kt++) {
        if (kt == NS - 1) { CP_WAIT0(); } else { CP_WAIT1(); }
        __syncthreads();
        if (kt + 2 < NS) issue(kt + 2);
        mma_stage(sb, kt % 3, rA, aSel, rB, bSel, acc);
        __syncthreads();
    }

    // epilogue: bias + relu, split to g_h planes
    const int crow = lane >> 2, ccol = (lane & 3) * 2;
#pragma unroll
    for (int mi = 0; mi < 4; mi++)
#pragma unroll
        for (int h = 0; h < 2; h++) {
            const int ml = wm + mi * 16 + crow + h * 8;
            const int entm = sEnt[ml];
            if (entm < 0) continue;
            __nv_bfloat16* ohi = g_h_hi + (size_t)entm * HDIM + n0;
            __nv_bfloat16* olo = g_h_lo + (size_t)entm * HDIM + n0;
#pragma unroll
            for (int ni = 0; ni < 4; ni++) {
                const int tn = wn + ni * 8 + ccol;
                float v0 = fmaxf(acc[mi][ni][h * 2 + 0] + sBias[tn], 0.f);
                float v1 = fmaxf(acc[mi][ni][h * 2 + 1] + sBias[tn + 1], 0.f);
                __nv_bfloat16 h0, l0, h1, l1;
                bsplit(v0, h0, l0); bsplit(v1, h1, l1);
                *(uint32_t*)(ohi + tn) = pkb(h0, h1);
                *(uint32_t*)(olo + tn) = pkb(l0, l1);
            }
        }
}

// ---------------- GEMM2: part = w * (h @ W2t^T + b2) -------------------------
__global__ __launch_bounds__(256)
void gemm2_mma(const float* __restrict__ b2) {
    const int e = blockIdx.z;
    const int count = g_count[e];
    const int r0 = blockIdx.y * MT;
    if (r0 >= count) return;
    const int n0 = blockIdx.x * NT;

    extern __shared__ char smem[];
    const uint32_t sb = smem_u32(smem);
    const int t = threadIdx.x, wid = t >> 5, lane = t & 31;

    int*   sEnt  = (int*)(smem + OFF_ENT);
    float* sW    = (float*)(smem + OFF_W);
    float* sBias = (float*)(smem + OFF_BIAS);
    if (t < 128) {
        int pos = r0 + t;
        bool ok = (pos < count);
        sEnt[t]  = ok ? g_list[e * B_TOK + pos] : -1;
        sW[t]    = ok ? g_wlist[e * B_TOK + pos] : 0.f;
        sBias[t] = b2[(size_t)e * ODIM + n0 + t];
    }
    __syncthreads();

    const int r = t >> 1;
    const int half = t & 1;
    const int ent = sEnt[r];
    const int row = (ent < 0 ? 0 : ent);
    const __nv_bfloat16* aH = g_h_hi + (size_t)row * HDIM + half * 32;
    const __nv_bfloat16* aL = g_h_lo + (size_t)row * HDIM + half * 32;
    const __nv_bfloat16* bH = g_W2t_hi + ((size_t)e * ODIM + n0 + r) * HDIM + half * 32;
    const __nv_bfloat16* bL = g_W2t_lo + ((size_t)e * ODIM + n0 + r) * HDIM + half * 32;
    uint32_t swo[4];
    const uint32_t rowOff = (uint32_t)r * 128 + half * 64;
#pragma unroll
    for (int i = 0; i < 4; i++) swo[i] = SW(rowOff + 16 * i);

    auto issue = [&](int kt) {
        uint32_t dst = sb + OFF_T + (uint32_t)(kt % 3) * STAGE;
        const size_t ko = (size_t)kt * KC;
#pragma unroll
        for (int i = 0; i < 4; i++) {
            uint32_t d = dst + swo[i];
            CP16(d,             aH + ko + i * 8);
            CP16(d + PLANE,     aL + ko + i * 8);
            CP16(d + 2 * PLANE, bH + ko + i * 8);
            CP16(d + 3 * PLANE, bL + ko + i * 8);
        }
        CP_COMMIT();
    };

    const int wm = (wid >> 2) * 64, wn = (wid & 3) * 32;
    const int rA = wm + (lane & 7) + ((lane >> 3) & 1) * 8, aSel = (lane >> 4) & 1;
    const int rB = wn + (lane & 7) + ((lane >> 4) & 1) * 8, bSel = (lane >> 3) & 1;

    float acc[4][4][4];
#pragma unroll
    for (int a = 0; a < 4; a++)
#pragma unroll
        for (int bq = 0; bq < 4; bq++)
#pragma unroll
            for (int c = 0; c < 4; c++) acc[a][bq][c] = 0.f;

    const int NS = HDIM / KC;  // 32
    issue(0); issue(1);
    for (int kt = 0; kt < NS; kt++) {
        if (kt == NS - 1) { CP_WAIT0(); } else { CP_WAIT1(); }
        __syncthreads();
        if (kt + 2 < NS) issue(kt + 2);
        mma_stage(sb, kt % 3, rA, aSel, rB, bSel, acc);
        __syncthreads();
    }

    // epilogue: (acc + bias) * weight -> g_part
    const int crow = lane >> 2, ccol = (lane & 3) * 2;
#pragma unroll
    for (int mi = 0; mi < 4; mi++)
#pragma unroll
        for (int h = 0; h < 2; h++) {
            const int ml = wm + mi * 16 + crow + h * 8;
            const int entm = sEnt[ml];
            if (entm < 0) continue;
            const float wt = sW[ml];
            float* op = g_part + (size_t)entm * ODIM + n0;
#pragma unroll
            for (int ni = 0; ni < 4; ni++) {
                const int tn = wn + ni * 8 + ccol;
                float2 v;
                v.x = (acc[mi][ni][h * 2 + 0] + sBias[tn]) * wt;
                v.y = (acc[mi][ni][h * 2 + 1] + sBias[tn + 1]) * wt;
                *(float2*)(op + tn) = v;
            }
        }
}

// ============================ combine ========================================
__global__ void combine_kernel(float* __restrict__ out) {
    int idx = blockIdx.x * blockDim.x + threadIdx.x;
    const int OW = ODIM / 4;
    int b  = idx / OW;
    int o4 = idx - b * OW;
    const float4* p = reinterpret_cast<const float4*>(g_part);
    float4 u = p[(size_t)(2 * b) * OW + o4];
    float4 v = p[(size_t)(2 * b + 1) * OW + o4];
    float4 r;
    r.x = u.x + v.x; r.y = u.y + v.y; r.z = u.z + v.z; r.w = u.w + v.w;
    reinterpret_cast<float4*>(out)[idx] = r;
}

// ============================ launch =========================================
extern "C" void kernel_launch(void* const* d_in, const int* in_sizes, int n_in,
                              void* d_out, int out_size) {
    const float* x  = (const float*)d_in[0];
    const float* Wg = (const float*)d_in[1];
    const float* bg = (const float*)d_in[2];
    const float* W1 = (const float*)d_in[3];
    const float* b1 = (const float*)d_in[4];
    const float* W2 = (const float*)d_in[5];
    const float* b2 = (const float*)d_in[6];
    float* out = (float*)d_out;

    static int smem_set = 0;
    if (!smem_set) {
        cudaFuncSetAttribute(gemm1_mma, cudaFuncAttributeMaxDynamicSharedMemorySize, SMEM_BYTES);
        cudaFuncSetAttribute(gemm2_mma, cudaFuncAttributeMaxDynamicSharedMemorySize, SMEM_BYTES);
        smem_set = 1;
    }

    zero_counts_kernel<<<1, 32>>>();
    gate_kernel<<<B_TOK / 8, 256>>>(x, Wg, bg);

    convX_kernel<<<(B_TOK * DDIM / 4) / 256, 256>>>(x);
    convW1_kernel<<<dim3(HDIM / 32, DDIM / 32, NEXP), dim3(32, 8)>>>(W1);
    convW2_kernel<<<dim3(ODIM / 32, HDIM / 32, NEXP), dim3(32, 8)>>>(W2);

    gemm1_mma<<<dim3(HDIM / NT, B_TOK / MT, NEXP), 256, SMEM_BYTES>>>(b1);
    gemm2_mma<<<dim3(ODIM / NT, B_TOK / MT, NEXP), 256, SMEM_BYTES>>>(b2);

    combine_kernel<<<(B_TOK * ODIM / 4) / 256, 256>>>(out);
}

// round 6
// speedup vs baseline: 2.8782x; 1.3401x over previous
#include <cuda_runtime.h>
#include <cuda_fp16.h>
#include <cstdint>

#define B_TOK 8192
#define DDIM  1024
#define HDIM  2048
#define ODIM  1024
#define NEXP  8

#define MT 128
#define NT 256
#define KC 64

// ---------------- scratch (device globals: allocation-free rule) -------------
__device__ int   g_count[NEXP];
__device__ int   g_list[NEXP * B_TOK];     // entry = token*2 + slot
__device__ float g_wlist[NEXP * B_TOK];
__device__ alignas(128) __half g_x_hi[(size_t)B_TOK * DDIM];
__device__ alignas(128) __half g_x_lo[(size_t)B_TOK * DDIM];
__device__ alignas(128) __half g_W1t[(size_t)NEXP * HDIM * DDIM];  // [E][H][D] fp16
__device__ alignas(128) __half g_W2t[(size_t)NEXP * ODIM * HDIM];  // [E][O][H] fp16
__device__ alignas(128) __half g_h_hi[(size_t)2 * B_TOK * HDIM];   // [16384][H]
__device__ alignas(128) __half g_h_lo[(size_t)2 * B_TOK * HDIM];
__device__ float g_part[(size_t)2 * B_TOK * ODIM];

// ---------------- helpers ----------------------------------------------------
__device__ __forceinline__ uint32_t smem_u32(const void* p) {
    uint32_t a;
    asm("{ .reg .u64 t; cvta.to.shared.u64 t, %1; cvt.u32.u64 %0, t; }"
        : "=r"(a) : "l"(p));
    return a;
}
#define SW(o) ((o) ^ (((o) >> 3) & 0x70))

__device__ __forceinline__ void ldsm4(uint32_t* r, uint32_t a) {
    asm volatile("ldmatrix.sync.aligned.m8n8.x4.shared.b16 {%0,%1,%2,%3}, [%4];"
        : "=r"(r[0]), "=r"(r[1]), "=r"(r[2]), "=r"(r[3]) : "r"(a));
}
__device__ __forceinline__ void mma16816(float* c, const uint32_t* a, const uint32_t* b) {
    asm volatile("mma.sync.aligned.m16n8k16.row.col.f32.f16.f16.f32 "
        "{%0,%1,%2,%3}, {%4,%5,%6,%7}, {%8,%9}, {%0,%1,%2,%3};"
        : "+f"(c[0]), "+f"(c[1]), "+f"(c[2]), "+f"(c[3])
        : "r"(a[0]), "r"(a[1]), "r"(a[2]), "r"(a[3]), "r"(b[0]), "r"(b[1]));
}
#define CP16(dst, src) \
    asm volatile("cp.async.cg.shared.global [%0], [%1], 16;" :: "r"(dst), "l"(src))
#define CP_COMMIT() asm volatile("cp.async.commit_group;" ::: "memory")
#define CP_WAIT1()  asm volatile("cp.async.wait_group 1;" ::: "memory")
#define CP_WAIT0()  asm volatile("cp.async.wait_group 0;" ::: "memory")

__device__ __forceinline__ void hsplit(float v, __half& h, __half& l) {
    h = __float2half_rn(v);
    l = __float2half_rn(v - __half2float(h));
}
__device__ __forceinline__ uint32_t pkh(__half a, __half b) {
    return (uint32_t)__half_as_ushort(a) | ((uint32_t)__half_as_ushort(b) << 16);
}

// ---------------- SMEM layout ------------------------------------------------
// [0,512) sEnt  [512,1024) sW  [1024,2048) sBias (256 floats)
// [2048, +3*64K): stages, each = [AH 16K | AL 16K | B 32K]
#define OFF_ENT  0
#define OFF_W    512
#define OFF_BIAS 1024
#define OFF_T    2048
#define A_PLANE  16384
#define B_OFF    32768
#define STAGE    65536
#define SMEM_BYTES (OFF_T + 3 * STAGE)   // 198656

// ============================ gating =========================================
__global__ void zero_counts_kernel() {
    if (threadIdx.x < NEXP) g_count[threadIdx.x] = 0;
}

__global__ void gate_kernel(const float* __restrict__ x,
                            const float* __restrict__ Wg,
                            const float* __restrict__ bg) {
    int gw   = (blockIdx.x * blockDim.x + threadIdx.x) >> 5;
    int lane = threadIdx.x & 31;
    if (gw >= B_TOK) return;
    const float* xr = x + (size_t)gw * DDIM;
    float acc[NEXP];
#pragma unroll
    for (int e = 0; e < NEXP; e++) acc[e] = 0.f;
    for (int d = lane; d < DDIM; d += 32) {
        float xv = xr[d];
        const float4* w4 = reinterpret_cast<const float4*>(Wg + (size_t)d * NEXP);
        float4 w0 = w4[0], w1 = w4[1];
        acc[0] += xv * w0.x; acc[1] += xv * w0.y;
        acc[2] += xv * w0.z; acc[3] += xv * w0.w;
        acc[4] += xv * w1.x; acc[5] += xv * w1.y;
        acc[6] += xv * w1.z; acc[7] += xv * w1.w;
    }
#pragma unroll
    for (int off = 16; off; off >>= 1)
#pragma unroll
        for (int e = 0; e < NEXP; e++)
            acc[e] += __shfl_xor_sync(0xFFFFFFFFu, acc[e], off);
    if (lane == 0) {
        float s[NEXP];
#pragma unroll
        for (int e = 0; e < NEXP; e++) s[e] = acc[e] + bg[e];
        float M = s[0];
#pragma unroll
        for (int e = 1; e < NEXP; e++) M = fmaxf(M, s[e]);
        float p[NEXP], Z = 0.f;
#pragma unroll
        for (int e = 0; e < NEXP; e++) { p[e] = expf(s[e] - M); Z += p[e]; }
        int i1 = 0;
#pragma unroll
        for (int e = 1; e < NEXP; e++) if (s[e] > s[i1]) i1 = e;
        int i2 = -1;
#pragma unroll
        for (int e = 0; e < NEXP; e++)
            if (e != i1 && (i2 < 0 || s[e] > s[i2])) i2 = e;
        float denom = p[i1] + p[i2] + 1e-8f * Z;
        float w1 = p[i1] / denom;
        float w2 = p[i2] / denom;
        int pos1 = atomicAdd(&g_count[i1], 1);
        g_list[i1 * B_TOK + pos1]  = gw * 2 + 0;
        g_wlist[i1 * B_TOK + pos1] = w1;
        int pos2 = atomicAdd(&g_count[i2], 1);
        g_list[i2 * B_TOK + pos2]  = gw * 2 + 1;
        g_wlist[i2 * B_TOK + pos2] = w2;
    }
}

// ============ conversions ====================================================
__global__ void convX_kernel(const float* __restrict__ x) {
    size_t idx = (size_t)blockIdx.x * blockDim.x + threadIdx.x;  // over B*D/4
    float4 v = reinterpret_cast<const float4*>(x)[idx];
    __half h0, h1, h2, h3, l0, l1, l2, l3;
    hsplit(v.x, h0, l0); hsplit(v.y, h1, l1);
    hsplit(v.z, h2, l2); hsplit(v.w, h3, l3);
    reinterpret_cast<uint2*>(g_x_hi)[idx] = make_uint2(pkh(h0, h1), pkh(h2, h3));
    reinterpret_cast<uint2*>(g_x_lo)[idx] = make_uint2(pkh(l0, l1), pkh(l2, l3));
}

__global__ void convW1_kernel(const float* __restrict__ W1) {
    __shared__ float ts[32][33];
    int e = blockIdx.z;
    int h0 = blockIdx.x * 32, d0 = blockIdx.y * 32;
    int tx = threadIdx.x, ty = threadIdx.y;
    const float* src = W1 + ((size_t)e * DDIM + d0) * HDIM + h0;
#pragma unroll
    for (int j = 0; j < 4; j++)
        ts[ty + 8 * j][tx] = src[(size_t)(ty + 8 * j) * HDIM + tx];
    __syncthreads();
#pragma unroll
    for (int j = 0; j < 4; j++) {
        int h = h0 + ty + 8 * j;
        g_W1t[((size_t)e * HDIM + h) * DDIM + d0 + tx] =
            __float2half_rn(ts[tx][ty + 8 * j]);
    }
}

__global__ void convW2_kernel(const float* __restrict__ W2) {
    __shared__ float ts[32][33];
    int e = blockIdx.z;
    int o0 = blockIdx.x * 32, h0 = blockIdx.y * 32;
    int tx = threadIdx.x, ty = threadIdx.y;
    const float* src = W2 + ((size_t)e * HDIM + h0) * ODIM + o0;
#pragma unroll
    for (int j = 0; j < 4; j++)
        ts[ty + 8 * j][tx] = src[(size_t)(ty + 8 * j) * ODIM + tx];
    __syncthreads();
#pragma unroll
    for (int j = 0; j < 4; j++) {
        int o = o0 + ty + 8 * j;
        g_W2t[((size_t)e * ODIM + o) * HDIM + h0 + tx] =
            __float2half_rn(ts[tx][ty + 8 * j]);
    }
}

// ============================ GEMM core ======================================
// 8 warps in 2x4 grid; warp tile 64x64; 2 passes (Ah*B then Al*B), pass-outer.
__device__ __forceinline__ void mma_stage(uint32_t sb, int st,
                                          int rA, int aSel, int rB, int bSel,
                                          float acc[4][8][4]) {
    const uint32_t AH = sb + OFF_T + (uint32_t)st * STAGE;
    const uint32_t AL = AH + A_PLANE;
    const uint32_t BB = AH + B_OFF;
#pragma unroll
    for (int k16 = 0; k16 < 4; k16++) {
        const uint32_t kb = k16 * 32;
        uint32_t bf[4][4], ah[4][4], al[4][4];
#pragma unroll
        for (int g = 0; g < 4; g++)
            ldsm4(bf[g], BB + SW((uint32_t)(rB + g * 16) * 128 + kb + bSel * 16));
#pragma unroll
        for (int mi = 0; mi < 4; mi++) {
            uint32_t off = SW((uint32_t)(rA + mi * 16) * 128 + kb + aSel * 16);
            ldsm4(ah[mi], AH + off);
            ldsm4(al[mi], AL + off);
        }
        // pass 1: Ah*B
#pragma unroll
        for (int mi = 0; mi < 4; mi++)
#pragma unroll
            for (int ni = 0; ni < 8; ni++)
                mma16816(acc[mi][ni], ah[mi], &bf[ni >> 1][(ni & 1) * 2]);
        // pass 2: Al*B
#pragma unroll
        for (int mi = 0; mi < 4; mi++)
#pragma unroll
            for (int ni = 0; ni < 8; ni++)
                mma16816(acc[mi][ni], al[mi], &bf[ni >> 1][(ni & 1) * 2]);
    }
}

// ---------------- GEMM1: h = relu(x_g @ W1t^T + b1) --------------------------
__global__ __launch_bounds__(256, 1)
void gemm1_mma(const float* __restrict__ b1) {
    const int e = blockIdx.z;
    const int count = g_count[e];
    const int r0 = blockIdx.y * MT;
    if (r0 >= count) return;
    const int n0 = blockIdx.x * NT;

    extern __shared__ char smem[];
    const uint32_t sb = smem_u32(smem);
    const int t = threadIdx.x, wid = t >> 5, lane = t & 31;

    int*   sEnt  = (int*)(smem + OFF_ENT);
    float* sBias = (float*)(smem + OFF_BIAS);
    if (t < 128) {
        int pos = r0 + t;
        sEnt[t]  = (pos < count) ? g_list[e * B_TOK + pos] : -1;
    }
    sBias[t] = b1[(size_t)e * HDIM + n0 + t];
    __syncthreads();

    // A copy coords: row r = t>>1 (0..127), 64B half (t&1)
    const int r = t >> 1;
    const int half = t & 1;
    const int ent = sEnt[r];
    const int tok = (ent < 0 ? 0 : ent) >> 1;
    const __half* aH = g_x_hi + (size_t)tok * DDIM + half * 32;
    const __half* aL = g_x_lo + (size_t)tok * DDIM + half * 32;
    uint32_t aswo[4];
    const uint32_t arow = (uint32_t)r * 128 + half * 64;
#pragma unroll
    for (int i = 0; i < 4; i++) aswo[i] = SW(arow + 16 * i);
    // B copy coords: row t (0..255), 8 x 16B chunks
    const __half* bW = g_W1t + ((size_t)e * HDIM + n0 + t) * DDIM;
    uint32_t bswo[8];
#pragma unroll
    for (int i = 0; i < 8; i++) bswo[i] = SW((uint32_t)t * 128 + 16 * i);

    auto issue = [&](int kt) {
        uint32_t dst = sb + OFF_T + (uint32_t)(kt % 3) * STAGE;
        const size_t ko = (size_t)kt * KC;
#pragma unroll
        for (int i = 0; i < 4; i++) {
            CP16(dst + aswo[i],           aH + ko + i * 8);
            CP16(dst + A_PLANE + aswo[i], aL + ko + i * 8);
        }
#pragma unroll
        for (int i = 0; i < 8; i++)
            CP16(dst + B_OFF + bswo[i], bW + ko + i * 8);
        CP_COMMIT();
    };

    const int wm = (wid >> 2) * 64, wn = (wid & 3) * 64;
    const int rA = wm + (lane & 7) + ((lane >> 3) & 1) * 8, aSel = (lane >> 4) & 1;
    const int rB = wn + (lane & 7) + ((lane >> 4) & 1) * 8, bSel = (lane >> 3) & 1;

    float acc[4][8][4];
#pragma unroll
    for (int a = 0; a < 4; a++)
#pragma unroll
        for (int bq = 0; bq < 8; bq++)
#pragma unroll
            for (int c = 0; c < 4; c++) acc[a][bq][c] = 0.f;

    const int NS = DDIM / KC;  // 16
    issue(0); issue(1);
    for (int kt = 0; kt < NS; kt++) {
        if (kt == NS - 1) { CP_WAIT0(); } else { CP_WAIT1(); }
        __syncthreads();
        if (kt + 2 < NS) issue(kt + 2);
        mma_stage(sb, kt % 3, rA, aSel, rB, bSel, acc);
        __syncthreads();
    }

    // epilogue: bias + relu, fp16 split to g_h planes
    const int crow = lane >> 2, ccol = (lane & 3) * 2;
#pragma unroll
    for (int mi = 0; mi < 4; mi++)
#pragma unroll
        for (int h = 0; h < 2; h++) {
            const int ml = wm + mi * 16 + crow + h * 8;
            const int entm = sEnt[ml];
            if (entm < 0) continue;
            __half* ohi = g_h_hi + (size_t)entm * HDIM + n0;
            __half* olo = g_h_lo + (size_t)entm * HDIM + n0;
#pragma unroll
            for (int ni = 0; ni < 8; ni++) {
                const int tn = wn + ni * 8 + ccol;
                float v0 = fmaxf(acc[mi][ni][h * 2 + 0] + sBias[tn], 0.f);
                float v1 = fmaxf(acc[mi][ni][h * 2 + 1] + sBias[tn + 1], 0.f);
                __half h0, l0, h1, l1;
                hsplit(v0, h0, l0); hsplit(v1, h1, l1);
                *(uint32_t*)(ohi + tn) = pkh(h0, h1);
                *(uint32_t*)(olo + tn) = pkh(l0, l1);
            }
        }
}

// ---------------- GEMM2: part = w * (h @ W2t^T + b2) -------------------------
__global__ __launch_bounds__(256, 1)
void gemm2_mma(const float* __restrict__ b2) {
    const int e = blockIdx.z;
    const int count = g_count[e];
    const int r0 = blockIdx.y * MT;
    if (r0 >= count) return;
    const int n0 = blockIdx.x * NT;

    extern __shared__ char smem[];
    const uint32_t sb = smem_u32(smem);
    const int t = threadIdx.x, wid = t >> 5, lane = t & 31;

    int*   sEnt  = (int*)(smem + OFF_ENT);
    float* sW    = (float*)(smem + OFF_W);
    float* sBias = (float*)(smem + OFF_BIAS);
    if (t < 128) {
        int pos = r0 + t;
        bool ok = (pos < count);
        sEnt[t]  = ok ? g_list[e * B_TOK + pos] : -1;
        sW[t]    = ok ? g_wlist[e * B_TOK + pos] : 0.f;
    }
    sBias[t] = b2[(size_t)e * ODIM + n0 + t];
    __syncthreads();

    const int r = t >> 1;
    const int half = t & 1;
    const int ent = sEnt[r];
    const int row = (ent < 0 ? 0 : ent);
    const __half* aH = g_h_hi + (size_t)row * HDIM + half * 32;
    const __half* aL = g_h_lo + (size_t)row * HDIM + half * 32;
    uint32_t aswo[4];
    const uint32_t arow = (uint32_t)r * 128 + half * 64;
#pragma unroll
    for (int i = 0; i < 4; i++) aswo[i] = SW(arow + 16 * i);
    const __half* bW = g_W2t + ((size_t)e * ODIM + n0 + t) * HDIM;
    uint32_t bswo[8];
#pragma unroll
    for (int i = 0; i < 8; i++) bswo[i] = SW((uint32_t)t * 128 + 16 * i);

    auto issue = [&](int kt) {
        uint32_t dst = sb + OFF_T + (uint32_t)(kt % 3) * STAGE;
        const size_t ko = (size_t)kt * KC;
#pragma unroll
        for (int i = 0; i < 4; i++) {
            CP16(dst + aswo[i],           aH + ko + i * 8);
            CP16(dst + A_PLANE + aswo[i], aL + ko + i * 8);
        }
#pragma unroll
        for (int i = 0; i < 8; i++)
            CP16(dst + B_OFF + bswo[i], bW + ko + i * 8);
        CP_COMMIT();
    };

    const int wm = (wid >> 2) * 64, wn = (wid & 3) * 64;
    const int rA = wm + (lane & 7) + ((lane >> 3) & 1) * 8, aSel = (lane >> 4) & 1;
    const int rB = wn + (lane & 7) + ((lane >> 4) & 1) * 8, bSel = (lane >> 3) & 1;

    float acc[4][8][4];
#pragma unroll
    for (int a = 0; a < 4; a++)
#pragma unroll
        for (int bq = 0; bq < 8; bq++)
#pragma unroll
            for (int c = 0; c < 4; c++) acc[a][bq][c] = 0.f;

    const int NS = HDIM / KC;  // 32
    issue(0); issue(1);
    for (int kt = 0; kt < NS; kt++) {
        if (kt == NS - 1) { CP_WAIT0(); } else { CP_WAIT1(); }
        __syncthreads();
        if (kt + 2 < NS) issue(kt + 2);
        mma_stage(sb, kt % 3, rA, aSel, rB, bSel, acc);
        __syncthreads();
    }

    // epilogue: (acc + bias) * weight -> g_part
    const int crow = lane >> 2, ccol = (lane & 3) * 2;
#pragma unroll
    for (int mi = 0; mi < 4; mi++)
#pragma unroll
        for (int h = 0; h < 2; h++) {
            const int ml = wm + mi * 16 + crow + h * 8;
            const int entm = sEnt[ml];
            if (entm < 0) continue;
            const float wt = sW[ml];
            float* op = g_part + (size_t)entm * ODIM + n0;
#pragma unroll
            for (int ni = 0; ni < 8; ni++) {
                const int tn = wn + ni * 8 + ccol;
                float2 v;
                v.x = (acc[mi][ni][h * 2 + 0] + sBias[tn]) * wt;
                v.y = (acc[mi][ni][h * 2 + 1] + sBias[tn + 1]) * wt;
                *(float2*)(op + tn) = v;
            }
        }
}

// ============================ combine ========================================
__global__ void combine_kernel(float* __restrict__ out) {
    int idx = blockIdx.x * blockDim.x + threadIdx.x;
    const int OW = ODIM / 4;
    int b  = idx / OW;
    int o4 = idx - b * OW;
    const float4* p = reinterpret_cast<const float4*>(g_part);
    float4 u = p[(size_t)(2 * b) * OW + o4];
    float4 v = p[(size_t)(2 * b + 1) * OW + o4];
    float4 r;
    r.x = u.x + v.x; r.y = u.y + v.y; r.z = u.z + v.z; r.w = u.w + v.w;
    reinterpret_cast<float4*>(out)[idx] = r;
}

// ============================ launch =========================================
extern "C" void kernel_launch(void* const* d_in, const int* in_sizes, int n_in,
                              void* d_out, int out_size) {
    const float* x  = (const float*)d_in[0];
    const float* Wg = (const float*)d_in[1];
    const float* bg = (const float*)d_in[2];
    const float* W1 = (const float*)d_in[3];
    const float* b1 = (const float*)d_in[4];
    const float* W2 = (const float*)d_in[5];
    const float* b2 = (const float*)d_in[6];
    float* out = (float*)d_out;

    static int smem_set = 0;
    if (!smem_set) {
        cudaFuncSetAttribute(gemm1_mma, cudaFuncAttributeMaxDynamicSharedMemorySize, SMEM_BYTES);
        cudaFuncSetAttribute(gemm2_mma, cudaFuncAttributeMaxDynamicSharedMemorySize, SMEM_BYTES);
        smem_set = 1;
    }

    zero_counts_kernel<<<1, 32>>>();
    gate_kernel<<<B_TOK / 8, 256>>>(x, Wg, bg);

    convX_kernel<<<(B_TOK * DDIM / 4) / 256, 256>>>(x);
    convW1_kernel<<<dim3(HDIM / 32, DDIM / 32, NEXP), dim3(32, 8)>>>(W1);
    convW2_kernel<<<dim3(ODIM / 32, HDIM / 32, NEXP), dim3(32, 8)>>>(W2);

    gemm1_mma<<<dim3(HDIM / NT, B_TOK / MT, NEXP), 256, SMEM_BYTES>>>(b1);
    gemm2_mma<<<dim3(ODIM / NT, B_TOK / MT, NEXP), 256, SMEM_BYTES>>>(b2);

    combine_kernel<<<(B_TOK * ODIM / 4) / 256, 256>>>(out);
}

// round 8
// speedup vs baseline: 4.3167x; 1.4998x over previous
#include <cuda_runtime.h>
#include <cuda_fp16.h>
#include <cstdint>

#define B_TOK 8192
#define DDIM  1024
#define HDIM  2048
#define ODIM  1024
#define NEXP  8

#define MT 128
#define NT 256
#define KC 64

// ---------------- scratch (device globals: allocation-free rule) -------------
__device__ int   g_count[NEXP];
__device__ int   g_list[NEXP * B_TOK];     // entry = token*2 + slot
__device__ float g_wlist[NEXP * B_TOK];
__device__ alignas(128) __half g_x16[(size_t)B_TOK * DDIM];
__device__ alignas(128) __half g_W1t[(size_t)NEXP * HDIM * DDIM];  // [E][H][D] fp16
__device__ alignas(128) __half g_W2t[(size_t)NEXP * ODIM * HDIM];  // [E][O][H] fp16
__device__ alignas(128) __half g_h16[(size_t)2 * B_TOK * HDIM];    // [16384][H]
__device__ float g_part[(size_t)2 * B_TOK * ODIM];

// ---------------- helpers ----------------------------------------------------
__device__ __forceinline__ uint32_t smem_u32(const void* p) {
    uint32_t a;
    asm("{ .reg .u64 t; cvta.to.shared.u64 t, %1; cvt.u32.u64 %0, t; }"
        : "=r"(a) : "l"(p));
    return a;
}
#define SW(o) ((o) ^ (((o) >> 3) & 0x70))

__device__ __forceinline__ void ldsm4(uint32_t* r, uint32_t a) {
    asm volatile("ldmatrix.sync.aligned.m8n8.x4.shared.b16 {%0,%1,%2,%3}, [%4];"
        : "=r"(r[0]), "=r"(r[1]), "=r"(r[2]), "=r"(r[3]) : "r"(a));
}
__device__ __forceinline__ void mma16816(float* c, const uint32_t* a, const uint32_t* b) {
    asm volatile("mma.sync.aligned.m16n8k16.row.col.f32.f16.f16.f32 "
        "{%0,%1,%2,%3}, {%4,%5,%6,%7}, {%8,%9}, {%0,%1,%2,%3};"
        : "+f"(c[0]), "+f"(c[1]), "+f"(c[2]), "+f"(c[3])
        : "r"(a[0]), "r"(a[1]), "r"(a[2]), "r"(a[3]), "r"(b[0]), "r"(b[1]));
}
#define CP16(dst, src) \
    asm volatile("cp.async.cg.shared.global [%0], [%1], 16;" :: "r"(dst), "l"(src))
#define CP_COMMIT() asm volatile("cp.async.commit_group;" ::: "memory")
#define CP_WAIT1()  asm volatile("cp.async.wait_group 1;" ::: "memory")
#define CP_WAIT0()  asm volatile("cp.async.wait_group 0;" ::: "memory")

__device__ __forceinline__ uint32_t pkh(__half a, __half b) {
    return (uint32_t)__half_as_ushort(a) | ((uint32_t)__half_as_ushort(b) << 16);
}

// ---------------- SMEM layout ------------------------------------------------
// [0,512) sEnt  [512,1024) sW  [1024,2048) sBias (256 floats)
// [2048, +3*48K): stages, each = [A 16K | B 32K]
#define OFF_ENT  0
#define OFF_W    512
#define OFF_BIAS 1024
#define OFF_T    2048
#define B_OFF    16384
#define STAGE    49152
#define SMEM_BYTES (OFF_T + 3 * STAGE)   // 149504

// ============================ gating =========================================
__global__ void zero_counts_kernel() {
    if (threadIdx.x < NEXP) g_count[threadIdx.x] = 0;
}

__global__ void gate_kernel(const float* __restrict__ x,
                            const float* __restrict__ Wg,
                            const float* __restrict__ bg) {
    int gw   = (blockIdx.x * blockDim.x + threadIdx.x) >> 5;
    int lane = threadIdx.x & 31;
    if (gw >= B_TOK) return;
    const float* xr = x + (size_t)gw * DDIM;
    float acc[NEXP];
#pragma unroll
    for (int e = 0; e < NEXP; e++) acc[e] = 0.f;
    for (int d = lane; d < DDIM; d += 32) {
        float xv = xr[d];
        const float4* w4 = reinterpret_cast<const float4*>(Wg + (size_t)d * NEXP);
        float4 w0 = w4[0], w1 = w4[1];
        acc[0] += xv * w0.x; acc[1] += xv * w0.y;
        acc[2] += xv * w0.z; acc[3] += xv * w0.w;
        acc[4] += xv * w1.x; acc[5] += xv * w1.y;
        acc[6] += xv * w1.z; acc[7] += xv * w1.w;
    }
#pragma unroll
    for (int off = 16; off; off >>= 1)
#pragma unroll
        for (int e = 0; e < NEXP; e++)
            acc[e] += __shfl_xor_sync(0xFFFFFFFFu, acc[e], off);
    if (lane == 0) {
        float s[NEXP];
#pragma unroll
        for (int e = 0; e < NEXP; e++) s[e] = acc[e] + bg[e];
        float M = s[0];
#pragma unroll
        for (int e = 1; e < NEXP; e++) M = fmaxf(M, s[e]);
        float p[NEXP], Z = 0.f;
#pragma unroll
        for (int e = 0; e < NEXP; e++) { p[e] = expf(s[e] - M); Z += p[e]; }
        int i1 = 0;
#pragma unroll
        for (int e = 1; e < NEXP; e++) if (s[e] > s[i1]) i1 = e;
        int i2 = -1;
#pragma unroll
        for (int e = 0; e < NEXP; e++)
            if (e != i1 && (i2 < 0 || s[e] > s[i2])) i2 = e;
        float denom = p[i1] + p[i2] + 1e-8f * Z;
        float w1 = p[i1] / denom;
        float w2 = p[i2] / denom;
        int pos1 = atomicAdd(&g_count[i1], 1);
        g_list[i1 * B_TOK + pos1]  = gw * 2 + 0;
        g_wlist[i1 * B_TOK + pos1] = w1;
        int pos2 = atomicAdd(&g_count[i2], 1);
        g_list[i2 * B_TOK + pos2]  = gw * 2 + 1;
        g_wlist[i2 * B_TOK + pos2] = w2;
    }
}

// ============ conversions ====================================================
__global__ void convX_kernel(const float* __restrict__ x) {
    size_t idx = (size_t)blockIdx.x * blockDim.x + threadIdx.x;  // over B*D/4
    float4 v = reinterpret_cast<const float4*>(x)[idx];
    reinterpret_cast<uint2*>(g_x16)[idx] =
        make_uint2(pkh(__float2half_rn(v.x), __float2half_rn(v.y)),
                   pkh(__float2half_rn(v.z), __float2half_rn(v.w)));
}

__global__ void convW1_kernel(const float* __restrict__ W1) {
    __shared__ float ts[32][33];
    int e = blockIdx.z;
    int h0 = blockIdx.x * 32, d0 = blockIdx.y * 32;
    int tx = threadIdx.x, ty = threadIdx.y;
    const float* src = W1 + ((size_t)e * DDIM + d0) * HDIM + h0;
#pragma unroll
    for (int j = 0; j < 4; j++)
        ts[ty + 8 * j][tx] = src[(size_t)(ty + 8 * j) * HDIM + tx];
    __syncthreads();
#pragma unroll
    for (int j = 0; j < 4; j++) {
        int h = h0 + ty + 8 * j;
        g_W1t[((size_t)e * HDIM + h) * DDIM + d0 + tx] =
            __float2half_rn(ts[tx][ty + 8 * j]);
    }
}

__global__ void convW2_kernel(const float* __restrict__ W2) {
    __shared__ float ts[32][33];
    int e = blockIdx.z;
    int o0 = blockIdx.x * 32, h0 = blockIdx.y * 32;
    int tx = threadIdx.x, ty = threadIdx.y;
    const float* src = W2 + ((size_t)e * HDIM + h0) * ODIM + o0;
#pragma unroll
    for (int j = 0; j < 4; j++)
        ts[ty + 8 * j][tx] = src[(size_t)(ty + 8 * j) * ODIM + tx];
    __syncthreads();
#pragma unroll
    for (int j = 0; j < 4; j++) {
        int o = o0 + ty + 8 * j;
        g_W2t[((size_t)e * ODIM + o) * HDIM + h0 + tx] =
            __float2half_rn(ts[tx][ty + 8 * j]);
    }
}

// ============================ GEMM core ======================================
// 8 warps in 2x4 grid; warp tile 64x64; single fp16 pass.
__device__ __forceinline__ void mma_stage(uint32_t sb, int st,
                                          int rA, int aSel, int rB, int bSel,
                                          float acc[4][8][4]) {
    const uint32_t AB = sb + OFF_T + (uint32_t)st * STAGE;
    const uint32_t BB = AB + B_OFF;
#pragma unroll
    for (int k16 = 0; k16 < 4; k16++) {
        const uint32_t kb = k16 * 32;
        uint32_t bf[4][4], af[4][4];
#pragma unroll
        for (int g = 0; g < 4; g++)
            ldsm4(bf[g], BB + SW((uint32_t)(rB + g * 16) * 128 + kb + bSel * 16));
#pragma unroll
        for (int mi = 0; mi < 4; mi++)
            ldsm4(af[mi], AB + SW((uint32_t)(rA + mi * 16) * 128 + kb + aSel * 16));
#pragma unroll
        for (int mi = 0; mi < 4; mi++)
#pragma unroll
            for (int ni = 0; ni < 8; ni++)
                mma16816(acc[mi][ni], af[mi], &bf[ni >> 1][(ni & 1) * 2]);
    }
}

// ---------------- GEMM1: h = relu(x_g @ W1t^T + b1) --------------------------
__global__ __launch_bounds__(256, 1)
void gemm1_mma(const float* __restrict__ b1) {
    const int e = blockIdx.z;
    const int count = g_count[e];
    const int r0 = blockIdx.y * MT;
    if (r0 >= count) return;
    const int n0 = blockIdx.x * NT;

    extern __shared__ char smem[];
    const uint32_t sb = smem_u32(smem);
    const int t = threadIdx.x, wid = t >> 5, lane = t & 31;

    int*   sEnt  = (int*)(smem + OFF_ENT);
    float* sBias = (float*)(smem + OFF_BIAS);
    if (t < 128) {
        int pos = r0 + t;
        sEnt[t]  = (pos < count) ? g_list[e * B_TOK + pos] : -1;
    }
    sBias[t] = b1[(size_t)e * HDIM + n0 + t];
    __syncthreads();

    // A copy coords: row r = t>>1 (0..127), 64B half (t&1)
    const int r = t >> 1;
    const int half = t & 1;
    const int ent = sEnt[r];
    const int tok = (ent < 0 ? 0 : ent) >> 1;
    const __half* aS = g_x16 + (size_t)tok * DDIM + half * 32;
    uint32_t aswo[4];
    const uint32_t arow = (uint32_t)r * 128 + half * 64;
#pragma unroll
    for (int i = 0; i < 4; i++) aswo[i] = SW(arow + 16 * i);
    // B copy coords: row t (0..255), 8 x 16B chunks
    const __half* bW = g_W1t + ((size_t)e * HDIM + n0 + t) * DDIM;
    uint32_t bswo[8];
#pragma unroll
    for (int i = 0; i < 8; i++) bswo[i] = SW((uint32_t)t * 128 + 16 * i);

    auto issue = [&](int kt) {
        uint32_t dst = sb + OFF_T + (uint32_t)(kt % 3) * STAGE;
        const size_t ko = (size_t)kt * KC;
#pragma unroll
        for (int i = 0; i < 4; i++)
            CP16(dst + aswo[i], aS + ko + i * 8);
#pragma unroll
        for (int i = 0; i < 8; i++)
            CP16(dst + B_OFF + bswo[i], bW + ko + i * 8);
        CP_COMMIT();
    };

    const int wm = (wid >> 2) * 64, wn = (wid & 3) * 64;
    const int rA = wm + (lane & 7) + ((lane >> 3) & 1) * 8, aSel = (lane >> 4) & 1;
    const int rB = wn + (lane & 7) + ((lane >> 4) & 1) * 8, bSel = (lane >> 3) & 1;

    float acc[4][8][4];
#pragma unroll
    for (int a = 0; a < 4; a++)
#pragma unroll
        for (int bq = 0; bq < 8; bq++)
#pragma unroll
            for (int c = 0; c < 4; c++) acc[a][bq][c] = 0.f;

    const int NS = DDIM / KC;  // 16
    issue(0); issue(1);
    for (int kt = 0; kt < NS; kt++) {
        if (kt == NS - 1) { CP_WAIT0(); } else { CP_WAIT1(); }
        __syncthreads();
        if (kt + 2 < NS) issue(kt + 2);
        mma_stage(sb, kt % 3, rA, aSel, rB, bSel, acc);
        __syncthreads();
    }

    // epilogue: bias + relu -> g_h16
    const int crow = lane >> 2, ccol = (lane & 3) * 2;
#pragma unroll
    for (int mi = 0; mi < 4; mi++)
#pragma unroll
        for (int h = 0; h < 2; h++) {
            const int ml = wm + mi * 16 + crow + h * 8;
            const int entm = sEnt[ml];
            if (entm < 0) continue;
            __half* oh = g_h16 + (size_t)entm * HDIM + n0;
#pragma unroll
            for (int ni = 0; ni < 8; ni++) {
                const int tn = wn + ni * 8 + ccol;
                float v0 = fmaxf(acc[mi][ni][h * 2 + 0] + sBias[tn], 0.f);
                float v1 = fmaxf(acc[mi][ni][h * 2 + 1] + sBias[tn + 1], 0.f);
                *(uint32_t*)(oh + tn) = pkh(__float2half_rn(v0), __float2half_rn(v1));
            }
        }
}

// ---------------- GEMM2: part = w * (h @ W2t^T + b2) -------------------------
__global__ __launch_bounds__(256, 1)
void gemm2_mma(const float* __restrict__ b2) {
    const int e = blockIdx.z;
    const int count = g_count[e];
    const int r0 = blockIdx.y * MT;
    if (r0 >= count) return;
    const int n0 = blockIdx.x * NT;

    extern __shared__ char smem[];
    const uint32_t sb = smem_u32(smem);
    const int t = threadIdx.x, wid = t >> 5, lane = t & 31;

    int*   sEnt  = (int*)(smem + OFF_ENT);
    float* sW    = (float*)(smem + OFF_W);
    float* sBias = (float*)(smem + OFF_BIAS);
    if (t < 128) {
        int pos = r0 + t;
        bool ok = (pos < count);
        sEnt[t]  = ok ? g_list[e * B_TOK + pos] : -1;
        sW[t]    = ok ? g_wlist[e * B_TOK + pos] : 0.f;
    }
    sBias[t] = b2[(size_t)e * ODIM + n0 + t];
    __syncthreads();

    const int r = t >> 1;
    const int half = t & 1;
    const int ent = sEnt[r];
    const int row = (ent < 0 ? 0 : ent);
    const __half* aS = g_h16 + (size_t)row * HDIM + half * 32;
    uint32_t aswo[4];
    const uint32_t arow = (uint32_t)r * 128 + half * 64;
#pragma unroll
    for (int i = 0; i < 4; i++) aswo[i] = SW(arow + 16 * i);
    const __half* bW = g_W2t + ((size_t)e * ODIM + n0 + t) * HDIM;
    uint32_t bswo[8];
#pragma unroll
    for (int i = 0; i < 8; i++) bswo[i] = SW((uint32_t)t * 128 + 16 * i);

    auto issue = [&](int kt) {
        uint32_t dst = sb + OFF_T + (uint32_t)(kt % 3) * STAGE;
        const size_t ko = (size_t)kt * KC;
#pragma unroll
        for (int i = 0; i < 4; i++)
            CP16(dst + aswo[i], aS + ko + i * 8);
#pragma unroll
        for (int i = 0; i < 8; i++)
            CP16(dst + B_OFF + bswo[i], bW + ko + i * 8);
        CP_COMMIT();
    };

    const int wm = (wid >> 2) * 64, wn = (wid & 3) * 64;
    const int rA = wm + (lane & 7) + ((lane >> 3) & 1) * 8, aSel = (lane >> 4) & 1;
    const int rB = wn + (lane & 7) + ((lane >> 4) & 1) * 8, bSel = (lane >> 3) & 1;

    float acc[4][8][4];
#pragma unroll
    for (int a = 0; a < 4; a++)
#pragma unroll
        for (int bq = 0; bq < 8; bq++)
#pragma unroll
            for (int c = 0; c < 4; c++) acc[a][bq][c] = 0.f;

    const int NS = HDIM / KC;  // 32
    issue(0); issue(1);
    for (int kt = 0; kt < NS; kt++) {
        if (kt == NS - 1) { CP_WAIT0(); } else { CP_WAIT1(); }
        __syncthreads();
        if (kt + 2 < NS) issue(kt + 2);
        mma_stage(sb, kt % 3, rA, aSel, rB, bSel, acc);
        __syncthreads();
    }

    // epilogue: (acc + bias) * weight -> g_part
    const int crow = lane >> 2, ccol = (lane & 3) * 2;
#pragma unroll
    for (int mi = 0; mi < 4; mi++)
#pragma unroll
        for (int h = 0; h < 2; h++) {
            const int ml = wm + mi * 16 + crow + h * 8;
            const int entm = sEnt[ml];
            if (entm < 0) continue;
            const float wt = sW[ml];
            float* op = g_part + (size_t)entm * ODIM + n0;
#pragma unroll
            for (int ni = 0; ni < 8; ni++) {
                const int tn = wn + ni * 8 + ccol;
                float2 v;
                v.x = (acc[mi][ni][h * 2 + 0] + sBias[tn]) * wt;
                v.y = (acc[mi][ni][h * 2 + 1] + sBias[tn + 1]) * wt;
                *(float2*)(op + tn) = v;
            }
        }
}

// ============================ combine ========================================
__global__ void combine_kernel(float* __restrict__ out) {
    int idx = blockIdx.x * blockDim.x + threadIdx.x;
    const int OW = ODIM / 4;
    int b  = idx / OW;
    int o4 = idx - b * OW;
    const float4* p = reinterpret_cast<const float4*>(g_part);
    float4 u = p[(size_t)(2 * b) * OW + o4];
    float4 v = p[(size_t)(2 * b + 1) * OW + o4];
    float4 r;
    r.x = u.x + v.x; r.y = u.y + v.y; r.z = u.z + v.z; r.w = u.w + v.w;
    reinterpret_cast<float4*>(out)[idx] = r;
}

// ============================ launch =========================================
extern "C" void kernel_launch(void* const* d_in, const int* in_sizes, int n_in,
                              void* d_out, int out_size) {
    const float* x  = (const float*)d_in[0];
    const float* Wg = (const float*)d_in[1];
    const float* bg = (const float*)d_in[2];
    const float* W1 = (const float*)d_in[3];
    const float* b1 = (const float*)d_in[4];
    const float* W2 = (const float*)d_in[5];
    const float* b2 = (const float*)d_in[6];
    float* out = (float*)d_out;

    static int smem_set = 0;
    if (!smem_set) {
        cudaFuncSetAttribute(gemm1_mma, cudaFuncAttributeMaxDynamicSharedMemorySize, SMEM_BYTES);
        cudaFuncSetAttribute(gemm2_mma, cudaFuncAttributeMaxDynamicSharedMemorySize, SMEM_BYTES);
        smem_set = 1;
    }

    zero_counts_kernel<<<1, 32>>>();
    gate_kernel<<<B_TOK / 8, 256>>>(x, Wg, bg);

    convX_kernel<<<(B_TOK * DDIM / 4) / 256, 256>>>(x);
    convW1_kernel<<<dim3(HDIM / 32, DDIM / 32, NEXP), dim3(32, 8)>>>(W1);
    convW2_kernel<<<dim3(ODIM / 32, HDIM / 32, NEXP), dim3(32, 8)>>>(W2);

    gemm1_mma<<<dim3(HDIM / NT, B_TOK / MT, NEXP), 256, SMEM_BYTES>>>(b1);
    gemm2_mma<<<dim3(ODIM / NT, B_TOK / MT, NEXP), 256, SMEM_BYTES>>>(b2);

    combine_kernel<<<(B_TOK * ODIM / 4) / 256, 256>>>(out);
}